// round 2
// baseline (speedup 1.0000x reference)
#include <cuda_runtime.h>

// Problem constants: B=2, F=16, C=256, H=W=32, L=4096, NH=4, ch=64
#define Tt   20480        // vlen + L
#define VLEN 16384        // F * H * W

typedef unsigned long long u64;

// ---------------- static device scratch (no allocations) ----------------
__device__ float g_stats[256];            // [s][b][g][{mu,rstd}]  (2*2*32*2)
__device__ float g_weff[4 * 768 * 256];   // folded GN*W per (s,b)
__device__ float g_beff[4 * 768];         // folded bias per (s,b)
__device__ float g_qkv[31457280];         // [b][o<768][t<T]  (~126 MB)
__device__ float g_attn[10485760];        // [b][c<256][t<T]  (~42 MB)

// ---------------- packed f32x2 helpers (Blackwell) ----------------
__device__ __forceinline__ u64 ffma2(u64 a, u64 b, u64 c) {
    u64 d; asm("fma.rn.f32x2 %0,%1,%2,%3;" : "=l"(d) : "l"(a), "l"(b), "l"(c)); return d;
}
__device__ __forceinline__ u64 fmul2(u64 a, u64 b) {
    u64 d; asm("mul.rn.f32x2 %0,%1,%2;" : "=l"(d) : "l"(a), "l"(b)); return d;
}
__device__ __forceinline__ u64 dup2(float x) {
    u64 d; unsigned r = __float_as_uint(x);
    asm("mov.b64 %0,{%1,%1};" : "=l"(d) : "r"(r)); return d;
}
__device__ __forceinline__ u64 pack2(float lo, float hi) {
    u64 d;
    asm("mov.b64 %0,{%1,%2};" : "=l"(d) : "r"(__float_as_uint(lo)), "r"(__float_as_uint(hi)));
    return d;
}
__device__ __forceinline__ float2 unpk(u64 v) {
    unsigned lo, hi; asm("mov.b64 {%0,%1},%2;" : "=r"(lo), "=r"(hi) : "l"(v));
    return make_float2(__uint_as_float(lo), __uint_as_float(hi));
}

// ---------------- 1) GroupNorm stats: mean/rstd per (stream,b,group) ----------------
// grid 128 = 2 streams * 2 batches * 32 groups; 256 threads
__global__ __launch_bounds__(256) void stats_kernel(const float* __restrict__ video,
                                                    const float* __restrict__ audio) {
    int id = blockIdx.x;
    int s = id >> 6, rem = id & 63, b = rem >> 5, g = rem & 31;
    int tid = threadIdx.x;
    float sum = 0.f, sq = 0.f;
    if (s == 0) {
        // video group: channels [8g,8g+8) over f=16, hw=1024 -> 131072 floats
        const float* base = video + ((size_t)(b * 16) * 256 + g * 8) * 1024;
        for (int i = tid; i < 32768; i += 256) {
            int j = i * 4;
            int f = j >> 13, c = (j >> 10) & 7, hw = j & 1023;
            float4 v = *(const float4*)(base + (size_t)f * 262144 + c * 1024 + hw);
            sum += v.x + v.y + v.z + v.w;
            sq  += v.x * v.x + v.y * v.y + v.z * v.z + v.w * v.w;
        }
    } else {
        // audio group: channels [8g,8g+8) over l=4096 -> 32768 floats
        const float* base = audio + ((size_t)b * 256 + g * 8) * 4096;
        for (int i = tid; i < 8192; i += 256) {
            int j = i * 4;
            int c = j >> 12, t = j & 4095;
            float4 v = *(const float4*)(base + (size_t)c * 4096 + t);
            sum += v.x + v.y + v.z + v.w;
            sq  += v.x * v.x + v.y * v.y + v.z * v.z + v.w * v.w;
        }
    }
    for (int o = 16; o; o >>= 1) {
        sum += __shfl_xor_sync(0xffffffffu, sum, o);
        sq  += __shfl_xor_sync(0xffffffffu, sq, o);
    }
    __shared__ float ss[8], sqq[8];
    int w = tid >> 5;
    if ((tid & 31) == 0) { ss[w] = sum; sqq[w] = sq; }
    __syncthreads();
    if (tid == 0) {
        float S1 = 0.f, S2 = 0.f;
        for (int i = 0; i < 8; i++) { S1 += ss[i]; S2 += sqq[i]; }
        float N = (s == 0) ? 131072.f : 32768.f;
        float mu = S1 / N;
        float var = S2 / N - mu * mu;
        int idx = ((s * 2 + b) * 32 + g) * 2;
        g_stats[idx] = mu;
        g_stats[idx + 1] = rsqrtf(var + 1e-5f);
    }
}

// ---------------- 2) fold GN affine into QKV weights ----------------
// grid 3072 = 2 streams * 2 batches * 768 rows; 256 threads (one per input channel)
__global__ __launch_bounds__(256) void fold_kernel(
    const float* __restrict__ wv, const float* __restrict__ bv,
    const float* __restrict__ wa, const float* __restrict__ ba,
    const float* __restrict__ gvs, const float* __restrict__ gvb,
    const float* __restrict__ gas, const float* __restrict__ gab) {
    int bid = blockIdx.x;
    int s = bid / 1536;
    int r = bid % 1536;
    int b = r / 768;
    int o = r % 768;
    int c = threadIdx.x;
    const float* W  = s ? wa  : wv;
    const float* Bb = s ? ba  : bv;
    const float* sc = s ? gas : gvs;
    const float* bi = s ? gab : gvb;
    int g = c >> 3;
    int sb = ((s * 2 + b) * 32 + g) * 2;
    float mu = g_stats[sb], rs = g_stats[sb + 1];
    float alpha = sc[c] * rs;
    float beta = bi[c] - mu * alpha;
    float w = W[(size_t)o * 256 + c];
    g_weff[((size_t)(s * 2 + b) * 768 + o) * 256 + c] = w * alpha;
    float part = w * beta;
    for (int off = 16; off; off >>= 1) part += __shfl_xor_sync(0xffffffffu, part, off);
    __shared__ float red[8];
    if ((c & 31) == 0) red[c >> 5] = part;
    __syncthreads();
    if (c == 0) {
        float tot = Bb[o];
        for (int i = 0; i < 8; i++) tot += red[i];
        g_beff[(size_t)(s * 2 + b) * 768 + o] = tot;
    }
}

// ---------------- 3) QKV GEMM: g_qkv[b][o][t] = Weff @ X + beff ----------------
// grid (160, 12, 2) : t-tiles(128) x o-tiles(64) x batch; 256 threads, 4x8 per thread
__global__ __launch_bounds__(256) void qkv_gemm(const float* __restrict__ video,
                                                const float* __restrict__ audio) {
    __shared__ float As[16][64];
    __shared__ float Bs[16][128];
    int b  = blockIdx.z;
    int o0 = blockIdx.y * 64;
    int t0 = blockIdx.x * 128;
    int s  = (t0 >= VLEN);
    int tid = threadIdx.x, tx = tid & 15, ty = tid >> 4;
    const float* W = g_weff + (size_t)(s * 2 + b) * 768 * 256;
    const float* Bg; size_t bstride;
    if (s == 0) {
        int f = t0 >> 10;
        Bg = video + ((size_t)(b * 16 + f) * 256) * 1024 + (t0 & 1023);
        bstride = 1024;
    } else {
        Bg = audio + ((size_t)b * 256) * 4096 + (t0 - VLEN);
        bstride = 4096;
    }
    u64 acc2[4][4];
#pragma unroll
    for (int i = 0; i < 4; i++)
#pragma unroll
        for (int j = 0; j < 4; j++) acc2[i][j] = 0ull;

    for (int kk = 0; kk < 256; kk += 16) {
        {   // A tile: 64 rows x 16 k
            int m = tid >> 2, kq = (tid & 3) * 4;
            float4 w4 = *(const float4*)(W + (size_t)(o0 + m) * 256 + kk + kq);
            As[kq + 0][m] = w4.x; As[kq + 1][m] = w4.y;
            As[kq + 2][m] = w4.z; As[kq + 3][m] = w4.w;
        }
#pragma unroll
        for (int r = 0; r < 2; r++) {   // B tile: 16 k x 128 t
            int idx = tid + 256 * r;
            int k = idx >> 5, n4 = (idx & 31) * 4;
            *(float4*)&Bs[k][n4] = *(const float4*)(Bg + (size_t)(kk + k) * bstride + n4);
        }
        __syncthreads();
#pragma unroll
        for (int k = 0; k < 16; k++) {
            float4 a4 = *(const float4*)&As[k][ty * 4];
            ulonglong2 bA = *(const ulonglong2*)&Bs[k][tx * 8];
            ulonglong2 bB = *(const ulonglong2*)&Bs[k][tx * 8 + 4];
            u64 bp[4] = {bA.x, bA.y, bB.x, bB.y};
            u64 ad[4] = {dup2(a4.x), dup2(a4.y), dup2(a4.z), dup2(a4.w)};
#pragma unroll
            for (int i = 0; i < 4; i++)
#pragma unroll
                for (int j = 0; j < 4; j++)
                    acc2[i][j] = ffma2(ad[i], bp[j], acc2[i][j]);
        }
        __syncthreads();
    }
#pragma unroll
    for (int i = 0; i < 4; i++) {
        int o = o0 + ty * 4 + i;
        float be = g_beff[(size_t)(s * 2 + b) * 768 + o];
        float2 p0 = unpk(acc2[i][0]), p1 = unpk(acc2[i][1]);
        float2 p2 = unpk(acc2[i][2]), p3 = unpk(acc2[i][3]);
        float* op = g_qkv + ((size_t)b * 768 + o) * Tt + t0 + tx * 8;
        float4 r0 = make_float4(p0.x + be, p0.y + be, p1.x + be, p1.y + be);
        float4 r1 = make_float4(p2.x + be, p2.y + be, p3.x + be, p3.y + be);
        *(float4*)op = r0;
        *(float4*)(op + 4) = r1;
    }
}

// ---------------- 4) cross attention (both directions), flash-style ----------------
// grid (128, 5): x = unit (bh*16+f), y<4 -> video-query chunk y (256 q, 256 keys),
//                y==4 -> audio queries (256 q, 1024 keys). 256 threads, 1 query/thread.
__global__ __launch_bounds__(256) void attn_kernel() {
    __shared__ float Ks[64][68];
    __shared__ float Vs[64][68];
    int u  = blockIdx.x;
    int bh = u >> 4, f = u & 15;
    int b  = bh >> 2, h = bh & 3;
    int y  = blockIdx.y;
    int tid = threadIdx.x;
    int tq, tk0, nkeys;
    if (y < 4) { tq = f * 1024 + y * 256 + tid; tk0 = VLEN + f * 256; nkeys = 256; }
    else       { tq = VLEN + f * 256 + tid;     tk0 = f * 1024;       nkeys = 1024; }

    size_t baseq = ((size_t)b * 768 + h * 64) * Tt;
    const float* gq = g_qkv + baseq;
    const float* gk = g_qkv + baseq + (size_t)256 * Tt;
    const float* gv = g_qkv + baseq + (size_t)512 * Tt;

    // q (scale^2 = ch^-0.5 = 0.125 folded in), packed into f32x2 pairs
    u64 q2[32];
#pragma unroll
    for (int m = 0; m < 32; m++) {
        float a = gq[(size_t)(2 * m) * Tt + tq] * 0.125f;
        float c = gq[(size_t)(2 * m + 1) * Tt + tq] * 0.125f;
        q2[m] = pack2(a, c);
    }
    u64 out2[32];
#pragma unroll
    for (int m = 0; m < 32; m++) out2[m] = 0ull;
    float mrun = -1e30f, lrun = 0.f;

    for (int kc = 0; kc < nkeys; kc += 64) {
#pragma unroll
        for (int r = 0; r < 4; r++) {
            int idx = tid + 256 * r;
            int c = idx >> 4, j4 = (idx & 15) * 4;
            float4 k4 = *(const float4*)(gk + (size_t)c * Tt + tk0 + kc + j4);
            float4 v4 = *(const float4*)(gv + (size_t)c * Tt + tk0 + kc + j4);
            Ks[j4 + 0][c] = k4.x; Ks[j4 + 1][c] = k4.y;
            Ks[j4 + 2][c] = k4.z; Ks[j4 + 3][c] = k4.w;
            Vs[j4 + 0][c] = v4.x; Vs[j4 + 1][c] = v4.y;
            Vs[j4 + 2][c] = v4.z; Vs[j4 + 3][c] = v4.w;
        }
        __syncthreads();
#pragma unroll 1
        for (int sc = 0; sc < 64; sc += 8) {
            float s[8];
#pragma unroll
            for (int j = 0; j < 8; j++) {
                const ulonglong2* kr = (const ulonglong2*)&Ks[sc + j][0];
                u64 c0 = 0ull, c1 = 0ull, c2 = 0ull, c3 = 0ull;
#pragma unroll
                for (int i = 0; i < 8; i++) {
                    ulonglong2 ka = kr[2 * i];
                    ulonglong2 kb = kr[2 * i + 1];
                    c0 = ffma2(q2[4 * i + 0], ka.x, c0);
                    c1 = ffma2(q2[4 * i + 1], ka.y, c1);
                    c2 = ffma2(q2[4 * i + 2], kb.x, c2);
                    c3 = ffma2(q2[4 * i + 3], kb.y, c3);
                }
                float2 f0 = unpk(c0), f1 = unpk(c1), f2 = unpk(c2), f3 = unpk(c3);
                s[j] = ((f0.x + f0.y) + (f1.x + f1.y)) + ((f2.x + f2.y) + (f3.x + f3.y));
            }
            float mnew = mrun;
#pragma unroll
            for (int j = 0; j < 8; j++) mnew = fmaxf(mnew, s[j]);
            float corr = __expf(mrun - mnew);
            mrun = mnew;
            lrun *= corr;
            u64 corr2 = dup2(corr);
#pragma unroll
            for (int m = 0; m < 32; m++) out2[m] = fmul2(out2[m], corr2);
#pragma unroll
            for (int j = 0; j < 8; j++) {
                float p = __expf(s[j] - mnew);
                lrun += p;
                u64 p2 = dup2(p);
                const ulonglong2* vr = (const ulonglong2*)&Vs[sc + j][0];
#pragma unroll
                for (int i = 0; i < 16; i++) {
                    ulonglong2 vv = vr[i];
                    out2[2 * i + 0] = ffma2(p2, vv.x, out2[2 * i + 0]);
                    out2[2 * i + 1] = ffma2(p2, vv.y, out2[2 * i + 1]);
                }
            }
        }
        __syncthreads();
    }
    float inv = 1.f / lrun;
    size_t baseo = ((size_t)b * 256 + h * 64) * Tt;
#pragma unroll
    for (int m = 0; m < 32; m++) {
        float2 v = unpk(out2[m]);
        g_attn[baseo + (size_t)(2 * m) * Tt + tq]     = v.x * inv;
        g_attn[baseo + (size_t)(2 * m + 1) * Tt + tq] = v.y * inv;
    }
}

// ---------------- 5) output projection + residual, writes d_out ----------------
// grid (160, 4, 2); same tiling as qkv_gemm, M=256
__global__ __launch_bounds__(256) void proj_kernel(
    const float* __restrict__ video, const float* __restrict__ audio,
    const float* __restrict__ wvp, const float* __restrict__ bvp,
    const float* __restrict__ wap, const float* __restrict__ bap,
    float* __restrict__ out) {
    __shared__ float As[16][64];
    __shared__ float Bs[16][128];
    int b  = blockIdx.z;
    int o0 = blockIdx.y * 64;
    int t0 = blockIdx.x * 128;
    int s  = (t0 >= VLEN);
    int tid = threadIdx.x, tx = tid & 15, ty = tid >> 4;
    const float* W  = s ? wap : wvp;
    const float* bb = s ? bap : bvp;
    const float* Bg = g_attn + (size_t)b * 256 * Tt + t0;

    u64 acc2[4][4];
#pragma unroll
    for (int i = 0; i < 4; i++)
#pragma unroll
        for (int j = 0; j < 4; j++) acc2[i][j] = 0ull;

    for (int kk = 0; kk < 256; kk += 16) {
        {
            int m = tid >> 2, kq = (tid & 3) * 4;
            float4 w4 = *(const float4*)(W + (size_t)(o0 + m) * 256 + kk + kq);
            As[kq + 0][m] = w4.x; As[kq + 1][m] = w4.y;
            As[kq + 2][m] = w4.z; As[kq + 3][m] = w4.w;
        }
#pragma unroll
        for (int r = 0; r < 2; r++) {
            int idx = tid + 256 * r;
            int k = idx >> 5, n4 = (idx & 31) * 4;
            *(float4*)&Bs[k][n4] = *(const float4*)(Bg + (size_t)(kk + k) * Tt + n4);
        }
        __syncthreads();
#pragma unroll
        for (int k = 0; k < 16; k++) {
            float4 a4 = *(const float4*)&As[k][ty * 4];
            ulonglong2 bA = *(const ulonglong2*)&Bs[k][tx * 8];
            ulonglong2 bB = *(const ulonglong2*)&Bs[k][tx * 8 + 4];
            u64 bp[4] = {bA.x, bA.y, bB.x, bB.y};
            u64 ad[4] = {dup2(a4.x), dup2(a4.y), dup2(a4.z), dup2(a4.w)};
#pragma unroll
            for (int i = 0; i < 4; i++)
#pragma unroll
                for (int j = 0; j < 4; j++)
                    acc2[i][j] = ffma2(ad[i], bp[j], acc2[i][j]);
        }
        __syncthreads();
    }
#pragma unroll
    for (int i = 0; i < 4; i++) {
        int o = o0 + ty * 4 + i;
        float be = bb[o];
        float2 p0 = unpk(acc2[i][0]), p1 = unpk(acc2[i][1]);
        float2 p2 = unpk(acc2[i][2]), p3 = unpk(acc2[i][3]);
        float v[8] = {p0.x + be, p0.y + be, p1.x + be, p1.y + be,
                      p2.x + be, p2.y + be, p3.x + be, p3.y + be};
        if (s == 0) {
            int f = t0 >> 10;
            int hw = (t0 & 1023) + tx * 8;
            size_t addr = ((size_t)(b * 16 + f) * 256 + o) * 1024 + hw;
            float4 r0 = *(const float4*)(video + addr);
            float4 r1 = *(const float4*)(video + addr + 4);
            r0.x += v[0]; r0.y += v[1]; r0.z += v[2]; r0.w += v[3];
            r1.x += v[4]; r1.y += v[5]; r1.z += v[6]; r1.w += v[7];
            *(float4*)(out + addr) = r0;
            *(float4*)(out + addr + 4) = r1;
        } else {
            int ta = (t0 - VLEN) + tx * 8;
            size_t addr = ((size_t)b * 256 + o) * 4096 + ta;
            float4 r0 = *(const float4*)(audio + addr);
            float4 r1 = *(const float4*)(audio + addr + 4);
            r0.x += v[0]; r0.y += v[1]; r0.z += v[2]; r0.w += v[3];
            r1.x += v[4]; r1.y += v[5]; r1.z += v[6]; r1.w += v[7];
            float* ob = out + 8388608 + addr;   // audio output follows video output
            *(float4*)ob = r0;
            *(float4*)(ob + 4) = r1;
        }
    }
}

// ---------------- launch ----------------
extern "C" void kernel_launch(void* const* d_in, const int* in_sizes, int n_in,
                              void* d_out, int out_size) {
    const float* video  = (const float*)d_in[0];
    const float* audio  = (const float*)d_in[1];
    const float* gvs    = (const float*)d_in[2];
    const float* gvb    = (const float*)d_in[3];
    const float* gas    = (const float*)d_in[4];
    const float* gab    = (const float*)d_in[5];
    const float* w_vqkv = (const float*)d_in[6];
    const float* b_vqkv = (const float*)d_in[7];
    const float* w_aqkv = (const float*)d_in[8];
    const float* b_aqkv = (const float*)d_in[9];
    const float* w_vproj = (const float*)d_in[10];
    const float* b_vproj = (const float*)d_in[11];
    const float* w_aproj = (const float*)d_in[12];
    const float* b_aproj = (const float*)d_in[13];
    float* out = (float*)d_out;

    stats_kernel<<<128, 256>>>(video, audio);
    fold_kernel<<<3072, 256>>>(w_vqkv, b_vqkv, w_aqkv, b_aqkv, gvs, gvb, gas, gab);
    dim3 gq(160, 12, 2);
    qkv_gemm<<<gq, 256>>>(video, audio);
    dim3 ga(128, 5);
    attn_kernel<<<ga, 256>>>();
    dim3 gp(160, 4, 2);
    proj_kernel<<<gp, 256>>>(video, audio, w_vproj, b_vproj, w_aproj, b_aproj, out);
}

// round 5
// speedup vs baseline: 1.7067x; 1.7067x over previous
#include <cuda_runtime.h>
#include <cuda_bf16.h>
#include <cstdint>

// Problem constants: B=2, F=16, C=256, H=W=32, L=4096, NH=4, ch=64
#define Tt   20480        // vlen + L
#define VLEN 16384        // F * H * W

typedef unsigned long long u64;
typedef unsigned int u32;

// ---------------- static device scratch (no allocations) ----------------
__device__ float g_stats[256];                 // [s][b][g][{mu,rstd}]
__device__ float g_weff[4 * 768 * 256];        // folded GN*W per (s,b)
__device__ float g_beff[4 * 768];              // folded bias per (s,b)
__device__ __nv_bfloat16 g_qkvt[31457280];     // [b][{q,k,v}][h][t][64ch]  (63MB)
__device__ float g_attn[10485760];             // [b][c<256][t<T]  (~42 MB)

// ---------------- packed f32x2 helpers ----------------
__device__ __forceinline__ u64 ffma2(u64 a, u64 b, u64 c) {
    u64 d; asm("fma.rn.f32x2 %0,%1,%2,%3;" : "=l"(d) : "l"(a), "l"(b), "l"(c)); return d;
}
__device__ __forceinline__ u64 dup2(float x) {
    u64 d; unsigned r = __float_as_uint(x);
    asm("mov.b64 %0,{%1,%1};" : "=l"(d) : "r"(r)); return d;
}
__device__ __forceinline__ float2 unpk(u64 v) {
    unsigned lo, hi; asm("mov.b64 {%0,%1},%2;" : "=r"(lo), "=r"(hi) : "l"(v));
    return make_float2(__uint_as_float(lo), __uint_as_float(hi));
}

// ---------------- mma.sync bf16 helper (sm_80+, assembles on sm_100) ----------------
__device__ __forceinline__ void mma_bf16(float* c, const u32* a, u32 b0, u32 b1) {
    asm volatile("mma.sync.aligned.m16n8k16.row.col.f32.bf16.bf16.f32 "
        "{%0,%1,%2,%3}, {%4,%5,%6,%7}, {%8,%9}, {%0,%1,%2,%3};"
        : "+f"(c[0]), "+f"(c[1]), "+f"(c[2]), "+f"(c[3])
        : "r"(a[0]), "r"(a[1]), "r"(a[2]), "r"(a[3]), "r"(b0), "r"(b1));
}

// ---------------- 1) GroupNorm stats ----------------
__global__ __launch_bounds__(256) void stats_kernel(const float* __restrict__ video,
                                                    const float* __restrict__ audio) {
    int id = blockIdx.x;
    int s = id >> 6, rem = id & 63, b = rem >> 5, g = rem & 31;
    int tid = threadIdx.x;
    float sum = 0.f, sq = 0.f;
    if (s == 0) {
        const float* base = video + ((size_t)(b * 16) * 256 + g * 8) * 1024;
        for (int i = tid; i < 32768; i += 256) {
            int j = i * 4;
            int f = j >> 13, c = (j >> 10) & 7, hw = j & 1023;
            float4 v = *(const float4*)(base + (size_t)f * 262144 + c * 1024 + hw);
            sum += v.x + v.y + v.z + v.w;
            sq  += v.x * v.x + v.y * v.y + v.z * v.z + v.w * v.w;
        }
    } else {
        const float* base = audio + ((size_t)b * 256 + g * 8) * 4096;
        for (int i = tid; i < 8192; i += 256) {
            int j = i * 4;
            int c = j >> 12, t = j & 4095;
            float4 v = *(const float4*)(base + (size_t)c * 4096 + t);
            sum += v.x + v.y + v.z + v.w;
            sq  += v.x * v.x + v.y * v.y + v.z * v.z + v.w * v.w;
        }
    }
    for (int o = 16; o; o >>= 1) {
        sum += __shfl_xor_sync(0xffffffffu, sum, o);
        sq  += __shfl_xor_sync(0xffffffffu, sq, o);
    }
    __shared__ float ss[8], sqq[8];
    int w = tid >> 5;
    if ((tid & 31) == 0) { ss[w] = sum; sqq[w] = sq; }
    __syncthreads();
    if (tid == 0) {
        float S1 = 0.f, S2 = 0.f;
        for (int i = 0; i < 8; i++) { S1 += ss[i]; S2 += sqq[i]; }
        float N = (s == 0) ? 131072.f : 32768.f;
        float mu = S1 / N;
        float var = S2 / N - mu * mu;
        int idx = ((s * 2 + b) * 32 + g) * 2;
        g_stats[idx] = mu;
        g_stats[idx + 1] = rsqrtf(var + 1e-5f);
    }
}

// ---------------- 2) fold GN affine into QKV weights ----------------
__global__ __launch_bounds__(256) void fold_kernel(
    const float* __restrict__ wv, const float* __restrict__ bv,
    const float* __restrict__ wa, const float* __restrict__ ba,
    const float* __restrict__ gvs, const float* __restrict__ gvb,
    const float* __restrict__ gas, const float* __restrict__ gab) {
    int bid = blockIdx.x;
    int s = bid / 1536;
    int r = bid % 1536;
    int b = r / 768;
    int o = r % 768;
    int c = threadIdx.x;
    const float* W  = s ? wa  : wv;
    const float* Bb = s ? ba  : bv;
    const float* sc = s ? gas : gvs;
    const float* bi = s ? gab : gvb;
    int g = c >> 3;
    int sb = ((s * 2 + b) * 32 + g) * 2;
    float mu = g_stats[sb], rs = g_stats[sb + 1];
    float alpha = sc[c] * rs;
    float beta = bi[c] - mu * alpha;
    float w = W[(size_t)o * 256 + c];
    g_weff[((size_t)(s * 2 + b) * 768 + o) * 256 + c] = w * alpha;
    float part = w * beta;
    for (int off = 16; off; off >>= 1) part += __shfl_xor_sync(0xffffffffu, part, off);
    __shared__ float red[8];
    if ((c & 31) == 0) red[c >> 5] = part;
    __syncthreads();
    if (c == 0) {
        float tot = Bb[o];
        for (int i = 0; i < 8; i++) tot += red[i];
        g_beff[(size_t)(s * 2 + b) * 768 + o] = tot;
    }
}

// ---------------- 3) QKV GEMM -> bf16 transposed [b][s][h][t][ch] ----------------
__global__ __launch_bounds__(256) void qkv_gemm(const float* __restrict__ video,
                                                const float* __restrict__ audio) {
    __shared__ float As[16][64];
    __shared__ float Bs[16][128];
    int b  = blockIdx.z;
    int o0 = blockIdx.y * 64;
    int t0 = blockIdx.x * 128;
    int str = (t0 >= VLEN);
    int tid = threadIdx.x, tx = tid & 15, ty = tid >> 4;
    const float* W = g_weff + (size_t)(str * 2 + b) * 768 * 256;
    const float* Bg; size_t bstride;
    if (str == 0) {
        int f = t0 >> 10;
        Bg = video + ((size_t)(b * 16 + f) * 256) * 1024 + (t0 & 1023);
        bstride = 1024;
    } else {
        Bg = audio + ((size_t)b * 256) * 4096 + (t0 - VLEN);
        bstride = 4096;
    }
    u64 acc2[4][4];
#pragma unroll
    for (int i = 0; i < 4; i++)
#pragma unroll
        for (int j = 0; j < 4; j++) acc2[i][j] = 0ull;

    for (int kk = 0; kk < 256; kk += 16) {
        {
            int m = tid >> 2, kq = (tid & 3) * 4;
            float4 w4 = *(const float4*)(W + (size_t)(o0 + m) * 256 + kk + kq);
            As[kq + 0][m] = w4.x; As[kq + 1][m] = w4.y;
            As[kq + 2][m] = w4.z; As[kq + 3][m] = w4.w;
        }
#pragma unroll
        for (int r = 0; r < 2; r++) {
            int idx = tid + 256 * r;
            int k = idx >> 5, n4 = (idx & 31) * 4;
            *(float4*)&Bs[k][n4] = *(const float4*)(Bg + (size_t)(kk + k) * bstride + n4);
        }
        __syncthreads();
#pragma unroll
        for (int k = 0; k < 16; k++) {
            float4 a4 = *(const float4*)&As[k][ty * 4];
            ulonglong2 bA = *(const ulonglong2*)&Bs[k][tx * 8];
            ulonglong2 bB = *(const ulonglong2*)&Bs[k][tx * 8 + 4];
            u64 bp[4] = {bA.x, bA.y, bB.x, bB.y};
            u64 ad[4] = {dup2(a4.x), dup2(a4.y), dup2(a4.z), dup2(a4.w)};
#pragma unroll
            for (int i = 0; i < 4; i++)
#pragma unroll
                for (int j = 0; j < 4; j++)
                    acc2[i][j] = ffma2(ad[i], bp[j], acc2[i][j]);
        }
        __syncthreads();
    }
    int si = o0 >> 8;            // q/k/v
    int hh = (o0 >> 6) & 3;      // head
    float be[4];
#pragma unroll
    for (int i = 0; i < 4; i++)
        be[i] = g_beff[(size_t)(str * 2 + b) * 768 + o0 + ty * 4 + i];
    size_t rowbase = ((((size_t)b * 3 + si) * 4 + hh) * Tt + t0) * 64;
#pragma unroll
    for (int j = 0; j < 4; j++) {
        float2 v0 = unpk(acc2[0][j]), v1 = unpk(acc2[1][j]);
        float2 v2 = unpk(acc2[2][j]), v3 = unpk(acc2[3][j]);
#pragma unroll
        for (int part = 0; part < 2; part++) {
            int t = tx * 8 + 2 * j + part;
            float a = (part ? v0.y : v0.x) + be[0];
            float bq = (part ? v1.y : v1.x) + be[1];
            float cq = (part ? v2.y : v2.x) + be[2];
            float dq = (part ? v3.y : v3.x) + be[3];
            __nv_bfloat162* dst = (__nv_bfloat162*)(g_qkvt + rowbase + (size_t)t * 64 + ty * 4);
            dst[0] = __floats2bfloat162_rn(a, bq);
            dst[1] = __floats2bfloat162_rn(cq, dq);
        }
    }
}

// ---------------- 4) mma.sync attention (FA2 style) ----------------
// grid 1280 x 256 thr (8 warps x 16 queries = 128-query tile per CTA)
// id<1024: video (8 q-tiles/unit, 256 keys = 2 chunks of 128)
// id>=1024: audio (2 q-tiles/unit, 1024 keys = 8 chunks of 128)
#define NKC     128    // keys per smem chunk
#define KSTRIDE 72     // bf16 stride for Ks rows (64 + 8 pad)
#define VSTRIDE 136    // bf16 stride for Vt rows (128 + 8 pad)

__global__ __launch_bounds__(256, 2) void attn_mma() {
    __shared__ __nv_bfloat16 Ks[NKC * KSTRIDE];   // [key][ch]   18432 B
    __shared__ __nv_bfloat16 Vt[64 * VSTRIDE];    // [ch][key]   17408 B
    int tid = threadIdx.x;
    int lane = tid & 31, w = tid >> 5;
    int g = lane >> 2, qi = lane & 3;

    int id = blockIdx.x;
    int unit, qt, nchunks, tq0, tk0;
    if (id < 1024) { unit = id >> 3; qt = id & 7; nchunks = 2; }
    else { int i2 = id - 1024; unit = i2 >> 1; qt = i2 & 1; nchunks = 8; }
    int b = unit >> 6, h = (unit >> 4) & 3, f = unit & 15;
    if (id < 1024) { tq0 = f * 1024 + qt * 128; tk0 = VLEN + f * 256; }
    else           { tq0 = VLEN + f * 256 + qt * 128; tk0 = f * 1024; }

    size_t off_q = (((size_t)b * 3 + 0) * 4 + h) * (size_t)Tt * 64;
    size_t off_k = (((size_t)b * 3 + 1) * 4 + h) * (size_t)Tt * 64;
    size_t off_v = (((size_t)b * 3 + 2) * 4 + h) * (size_t)Tt * 64;

    // Q fragments: 4 k-steps of m16k16 (rows qbase+g, qbase+g+8)
    int qbase = tq0 + w * 16;
    u32 qa[4][4];
    {
        const __nv_bfloat16* q0 = g_qkvt + off_q + (size_t)(qbase + g) * 64;
        const __nv_bfloat16* q1 = g_qkvt + off_q + (size_t)(qbase + g + 8) * 64;
#pragma unroll
        for (int s = 0; s < 4; s++) {
            qa[s][0] = *(const u32*)(q0 + 16 * s + 2 * qi);
            qa[s][1] = *(const u32*)(q1 + 16 * s + 2 * qi);
            qa[s][2] = *(const u32*)(q0 + 16 * s + 2 * qi + 8);
            qa[s][3] = *(const u32*)(q1 + 16 * s + 2 * qi + 8);
        }
    }
    float ofr[8][4];
#pragma unroll
    for (int ct = 0; ct < 8; ct++)
        ofr[ct][0] = ofr[ct][1] = ofr[ct][2] = ofr[ct][3] = 0.f;
    float mlo_r = -1e30f, mhi_r = -1e30f, llo = 0.f, lhi = 0.f;

    for (int c = 0; c < nchunks; c++) {
        int kc = tk0 + c * NKC;
        // stage K [key][ch] and V transposed [ch][key]
        for (int m = tid; m < NKC * 8; m += 256) {
            int key = m >> 3, j = m & 7;
            uint4 kv = *(const uint4*)(g_qkvt + off_k + (size_t)(kc + key) * 64 + j * 8);
            *(uint4*)(Ks + key * KSTRIDE + j * 8) = kv;
            uint4 vv = *(const uint4*)(g_qkvt + off_v + (size_t)(kc + key) * 64 + j * 8);
            const __nv_bfloat16* pv = (const __nv_bfloat16*)&vv;
#pragma unroll
            for (int e = 0; e < 8; e++)
                Vt[(j * 8 + e) * VSTRIDE + key] = pv[e];
        }
        __syncthreads();

        for (int sc = 0; sc < NKC / 64; sc++) {
            // ---- S = Q @ K^T for 64 keys (8 n-tiles) ----
            float cfr[8][4];
#pragma unroll
            for (int nt = 0; nt < 8; nt++) {
                cfr[nt][0] = cfr[nt][1] = cfr[nt][2] = cfr[nt][3] = 0.f;
                const __nv_bfloat16* kr = Ks + (sc * 64 + nt * 8 + g) * KSTRIDE + 2 * qi;
#pragma unroll
                for (int s = 0; s < 4; s++) {
                    u32 b0 = *(const u32*)(kr + 16 * s);
                    u32 b1 = *(const u32*)(kr + 16 * s + 8);
                    mma_bf16(cfr[nt], qa[s], b0, b1);
                }
            }
            // ---- online softmax ----
            float mlo = -1e30f, mhi = -1e30f;
#pragma unroll
            for (int nt = 0; nt < 8; nt++) {
                mlo = fmaxf(mlo, fmaxf(cfr[nt][0], cfr[nt][1]));
                mhi = fmaxf(mhi, fmaxf(cfr[nt][2], cfr[nt][3]));
            }
            mlo *= 0.125f; mhi *= 0.125f;
            mlo = fmaxf(mlo, __shfl_xor_sync(0xffffffffu, mlo, 1));
            mlo = fmaxf(mlo, __shfl_xor_sync(0xffffffffu, mlo, 2));
            mhi = fmaxf(mhi, __shfl_xor_sync(0xffffffffu, mhi, 1));
            mhi = fmaxf(mhi, __shfl_xor_sync(0xffffffffu, mhi, 2));
            float nmlo = fmaxf(mlo_r, mlo), nmhi = fmaxf(mhi_r, mhi);
            float clo = __expf(mlo_r - nmlo), chi = __expf(mhi_r - nmhi);
            mlo_r = nmlo; mhi_r = nmhi;
            llo *= clo; lhi *= chi;
#pragma unroll
            for (int ct = 0; ct < 8; ct++) {
                ofr[ct][0] *= clo; ofr[ct][1] *= clo;
                ofr[ct][2] *= chi; ofr[ct][3] *= chi;
            }
            u32 plo[8], phi[8];
#pragma unroll
            for (int nt = 0; nt < 8; nt++) {
                float p0 = __expf(cfr[nt][0] * 0.125f - nmlo);
                float p1 = __expf(cfr[nt][1] * 0.125f - nmlo);
                float p2 = __expf(cfr[nt][2] * 0.125f - nmhi);
                float p3 = __expf(cfr[nt][3] * 0.125f - nmhi);
                llo += p0 + p1; lhi += p2 + p3;
                __nv_bfloat162 lo2 = __floats2bfloat162_rn(p0, p1);
                __nv_bfloat162 hi2 = __floats2bfloat162_rn(p2, p3);
                plo[nt] = *(u32*)&lo2; phi[nt] = *(u32*)&hi2;
            }
            // ---- O += P @ V  (S C-frag layout == PV A-frag layout) ----
#pragma unroll
            for (int s = 0; s < 4; s++) {
                u32 pa[4] = {plo[2 * s], phi[2 * s], plo[2 * s + 1], phi[2 * s + 1]};
                const __nv_bfloat16* vr = Vt + g * VSTRIDE + sc * 64 + 16 * s + 2 * qi;
#pragma unroll
                for (int ct = 0; ct < 8; ct++) {
                    u32 b0 = *(const u32*)(vr + ct * 8 * VSTRIDE);
                    u32 b1 = *(const u32*)(vr + ct * 8 * VSTRIDE + 8);
                    mma_bf16(ofr[ct], pa, b0, b1);
                }
            }
        }
        __syncthreads();
    }

    // ---- finalize ----
    llo += __shfl_xor_sync(0xffffffffu, llo, 1);
    llo += __shfl_xor_sync(0xffffffffu, llo, 2);
    lhi += __shfl_xor_sync(0xffffffffu, lhi, 1);
    lhi += __shfl_xor_sync(0xffffffffu, lhi, 2);
    float ilo = 1.f / llo, ihi = 1.f / lhi;
    size_t basec = (size_t)b * 256 + h * 64;
    int q0 = qbase + g, q1 = qbase + g + 8;
#pragma unroll
    for (int ct = 0; ct < 8; ct++) {
        int ch = ct * 8 + 2 * qi;
        size_t a0 = (basec + ch) * (size_t)Tt;
        g_attn[a0 + q0]      = ofr[ct][0] * ilo;
        g_attn[a0 + Tt + q0] = ofr[ct][1] * ilo;
        g_attn[a0 + q1]      = ofr[ct][2] * ihi;
        g_attn[a0 + Tt + q1] = ofr[ct][3] * ihi;
    }
}

// ---------------- 5) output projection + residual ----------------
__global__ __launch_bounds__(256) void proj_kernel(
    const float* __restrict__ video, const float* __restrict__ audio,
    const float* __restrict__ wvp, const float* __restrict__ bvp,
    const float* __restrict__ wap, const float* __restrict__ bap,
    float* __restrict__ out) {
    __shared__ float As[16][64];
    __shared__ float Bs[16][128];
    int b  = blockIdx.z;
    int o0 = blockIdx.y * 64;
    int t0 = blockIdx.x * 128;
    int s  = (t0 >= VLEN);
    int tid = threadIdx.x, tx = tid & 15, ty = tid >> 4;
    const float* W  = s ? wap : wvp;
    const float* bb = s ? bap : bvp;
    const float* Bg = g_attn + (size_t)b * 256 * Tt + t0;

    u64 acc2[4][4];
#pragma unroll
    for (int i = 0; i < 4; i++)
#pragma unroll
        for (int j = 0; j < 4; j++) acc2[i][j] = 0ull;

    for (int kk = 0; kk < 256; kk += 16) {
        {
            int m = tid >> 2, kq = (tid & 3) * 4;
            float4 w4 = *(const float4*)(W + (size_t)(o0 + m) * 256 + kk + kq);
            As[kq + 0][m] = w4.x; As[kq + 1][m] = w4.y;
            As[kq + 2][m] = w4.z; As[kq + 3][m] = w4.w;
        }
#pragma unroll
        for (int r = 0; r < 2; r++) {
            int idx = tid + 256 * r;
            int k = idx >> 5, n4 = (idx & 31) * 4;
            *(float4*)&Bs[k][n4] = *(const float4*)(Bg + (size_t)(kk + k) * Tt + n4);
        }
        __syncthreads();
#pragma unroll
        for (int k = 0; k < 16; k++) {
            float4 a4 = *(const float4*)&As[k][ty * 4];
            ulonglong2 bA = *(const ulonglong2*)&Bs[k][tx * 8];
            ulonglong2 bB = *(const ulonglong2*)&Bs[k][tx * 8 + 4];
            u64 bp[4] = {bA.x, bA.y, bB.x, bB.y};
            u64 ad[4] = {dup2(a4.x), dup2(a4.y), dup2(a4.z), dup2(a4.w)};
#pragma unroll
            for (int i = 0; i < 4; i++)
#pragma unroll
                for (int j = 0; j < 4; j++)
                    acc2[i][j] = ffma2(ad[i], bp[j], acc2[i][j]);
        }
        __syncthreads();
    }
#pragma unroll
    for (int i = 0; i < 4; i++) {
        int o = o0 + ty * 4 + i;
        float be = bb[o];
        float2 p0 = unpk(acc2[i][0]), p1 = unpk(acc2[i][1]);
        float2 p2 = unpk(acc2[i][2]), p3 = unpk(acc2[i][3]);
        float v[8] = {p0.x + be, p0.y + be, p1.x + be, p1.y + be,
                      p2.x + be, p2.y + be, p3.x + be, p3.y + be};
        if (s == 0) {
            int f = t0 >> 10;
            int hw = (t0 & 1023) + tx * 8;
            size_t addr = ((size_t)(b * 16 + f) * 256 + o) * 1024 + hw;
            float4 r0 = *(const float4*)(video + addr);
            float4 r1 = *(const float4*)(video + addr + 4);
            r0.x += v[0]; r0.y += v[1]; r0.z += v[2]; r0.w += v[3];
            r1.x += v[4]; r1.y += v[5]; r1.z += v[6]; r1.w += v[7];
            *(float4*)(out + addr) = r0;
            *(float4*)(out + addr + 4) = r1;
        } else {
            int ta = (t0 - VLEN) + tx * 8;
            size_t addr = ((size_t)b * 256 + o) * 4096 + ta;
            float4 r0 = *(const float4*)(audio + addr);
            float4 r1 = *(const float4*)(audio + addr + 4);
            r0.x += v[0]; r0.y += v[1]; r0.z += v[2]; r0.w += v[3];
            r1.x += v[4]; r1.y += v[5]; r1.z += v[6]; r1.w += v[7];
            float* ob = out + 8388608 + addr;
            *(float4*)ob = r0;
            *(float4*)(ob + 4) = r1;
        }
    }
}

// ---------------- launch ----------------
extern "C" void kernel_launch(void* const* d_in, const int* in_sizes, int n_in,
                              void* d_out, int out_size) {
    const float* video  = (const float*)d_in[0];
    const float* audio  = (const float*)d_in[1];
    const float* gvs    = (const float*)d_in[2];
    const float* gvb    = (const float*)d_in[3];
    const float* gas    = (const float*)d_in[4];
    const float* gab    = (const float*)d_in[5];
    const float* w_vqkv = (const float*)d_in[6];
    const float* b_vqkv = (const float*)d_in[7];
    const float* w_aqkv = (const float*)d_in[8];
    const float* b_aqkv = (const float*)d_in[9];
    const float* w_vproj = (const float*)d_in[10];
    const float* b_vproj = (const float*)d_in[11];
    const float* w_aproj = (const float*)d_in[12];
    const float* b_aproj = (const float*)d_in[13];
    float* out = (float*)d_out;

    stats_kernel<<<128, 256>>>(video, audio);
    fold_kernel<<<3072, 256>>>(w_vqkv, b_vqkv, w_aqkv, b_aqkv, gvs, gvb, gas, gab);
    dim3 gq(160, 12, 2);
    qkv_gemm<<<gq, 256>>>(video, audio);
    attn_mma<<<1280, 256>>>();
    dim3 gp(160, 4, 2);
    proj_kernel<<<gp, 256>>>(video, audio, w_vproj, b_vproj, w_aproj, b_aproj, out);
}

// round 7
// speedup vs baseline: 4.5969x; 2.6935x over previous
#include <cuda_runtime.h>
#include <cuda_bf16.h>
#include <cstdint>

// Problem constants: B=2, F=16, C=256, H=W=32, L=4096, NH=4, ch=64
#define Tt   20480        // vlen + L
#define VLEN 16384        // F * H * W

typedef unsigned long long u64;
typedef unsigned int u32;

// ---------------- static device scratch (no allocations) ----------------
__device__ float g_stats[256];                 // [s][b][g][{mu,rstd}]
__device__ __nv_bfloat16 g_weffh[4 * 768 * 256];  // folded GN*W per (s,b), bf16
__device__ float g_beff[4 * 768];              // folded bias per (s,b)
__device__ __nv_bfloat16 g_wprojh[2 * 256 * 256]; // proj weights bf16 [str][o][c]
__device__ __nv_bfloat16 g_qkvt[31457280];     // [b][{q,k,v}][h][t][64ch]  (63MB)
__device__ __nv_bfloat16 g_attnh[10485760];    // [b][t][256c]  (21MB)

// ---------------- mma.sync bf16 helper ----------------
__device__ __forceinline__ void mma_bf16(float* c, const u32* a, u32 b0, u32 b1) {
    asm volatile("mma.sync.aligned.m16n8k16.row.col.f32.bf16.bf16.f32 "
        "{%0,%1,%2,%3}, {%4,%5,%6,%7}, {%8,%9}, {%0,%1,%2,%3};"
        : "+f"(c[0]), "+f"(c[1]), "+f"(c[2]), "+f"(c[3])
        : "r"(a[0]), "r"(a[1]), "r"(a[2]), "r"(a[3]), "r"(b0), "r"(b1));
}
__device__ __forceinline__ u32 pack_bf16x2(float lo, float hi) {
    __nv_bfloat162 v = __floats2bfloat162_rn(lo, hi);
    return *(u32*)&v;
}

// ---------------- 1) GroupNorm stats ----------------
__global__ __launch_bounds__(256) void stats_kernel(const float* __restrict__ video,
                                                    const float* __restrict__ audio) {
    int id = blockIdx.x;
    int s = id >> 6, rem = id & 63, b = rem >> 5, g = rem & 31;
    int tid = threadIdx.x;
    float sum = 0.f, sq = 0.f;
    if (s == 0) {
        const float* base = video + ((size_t)(b * 16) * 256 + g * 8) * 1024;
        for (int i = tid; i < 32768; i += 256) {
            int j = i * 4;
            int f = j >> 13, c = (j >> 10) & 7, hw = j & 1023;
            float4 v = *(const float4*)(base + (size_t)f * 262144 + c * 1024 + hw);
            sum += v.x + v.y + v.z + v.w;
            sq  += v.x * v.x + v.y * v.y + v.z * v.z + v.w * v.w;
        }
    } else {
        const float* base = audio + ((size_t)b * 256 + g * 8) * 4096;
        for (int i = tid; i < 8192; i += 256) {
            int j = i * 4;
            int c = j >> 12, t = j & 4095;
            float4 v = *(const float4*)(base + (size_t)c * 4096 + t);
            sum += v.x + v.y + v.z + v.w;
            sq  += v.x * v.x + v.y * v.y + v.z * v.z + v.w * v.w;
        }
    }
    for (int o = 16; o; o >>= 1) {
        sum += __shfl_xor_sync(0xffffffffu, sum, o);
        sq  += __shfl_xor_sync(0xffffffffu, sq, o);
    }
    __shared__ float ss[8], sqq[8];
    int w = tid >> 5;
    if ((tid & 31) == 0) { ss[w] = sum; sqq[w] = sq; }
    __syncthreads();
    if (tid == 0) {
        float S1 = 0.f, S2 = 0.f;
        for (int i = 0; i < 8; i++) { S1 += ss[i]; S2 += sqq[i]; }
        float N = (s == 0) ? 131072.f : 32768.f;
        float mu = S1 / N;
        float var = S2 / N - mu * mu;
        int idx = ((s * 2 + b) * 32 + g) * 2;
        g_stats[idx] = mu;
        g_stats[idx + 1] = rsqrtf(var + 1e-5f);
    }
}

// ---------------- 2) fold GN affine into QKV weights (bf16 out) ----------------
__global__ __launch_bounds__(256) void fold_kernel(
    const float* __restrict__ wv, const float* __restrict__ bv,
    const float* __restrict__ wa, const float* __restrict__ ba,
    const float* __restrict__ gvs, const float* __restrict__ gvb,
    const float* __restrict__ gas, const float* __restrict__ gab) {
    int bid = blockIdx.x;
    int s = bid / 1536;
    int r = bid % 1536;
    int b = r / 768;
    int o = r % 768;
    int c = threadIdx.x;
    const float* W  = s ? wa  : wv;
    const float* Bb = s ? ba  : bv;
    const float* sc = s ? gas : gvs;
    const float* bi = s ? gab : gvb;
    int g = c >> 3;
    int sb = ((s * 2 + b) * 32 + g) * 2;
    float mu = g_stats[sb], rs = g_stats[sb + 1];
    float alpha = sc[c] * rs;
    float beta = bi[c] - mu * alpha;
    float w = W[(size_t)o * 256 + c];
    g_weffh[((size_t)(s * 2 + b) * 768 + o) * 256 + c] = __float2bfloat16(w * alpha);
    float part = w * beta;
    for (int off = 16; off; off >>= 1) part += __shfl_xor_sync(0xffffffffu, part, off);
    __shared__ float red[8];
    if ((c & 31) == 0) red[c >> 5] = part;
    __syncthreads();
    if (c == 0) {
        float tot = Bb[o];
        for (int i = 0; i < 8; i++) tot += red[i];
        g_beff[(size_t)(s * 2 + b) * 768 + o] = tot;
    }
}

// ---------------- 2b) convert proj weights to bf16 ----------------
__global__ __launch_bounds__(256) void wconv_kernel(const float* __restrict__ wvp,
                                                    const float* __restrict__ wap) {
    int i = blockIdx.x * 256 + threadIdx.x;   // grid 256 -> 65536
    g_wprojh[i] = __float2bfloat16(wvp[i]);
    g_wprojh[65536 + i] = __float2bfloat16(wap[i]);
}

// ---------------- 3) QKV GEMM via mma.sync: C = X^T @ W^T  (M=t, N=o) ----------------
// grid (320, 3, 2): x = 64-t tile, y = s (q/k/v), z = b. 256 thr = 8 warps.
__global__ __launch_bounds__(256, 2) void qkv_mma(const float* __restrict__ video,
                                                  const float* __restrict__ audio) {
    __shared__ __nv_bfloat16 Xs[64][264];   // [t][c] transposed input, 33792 B
    int b = blockIdx.z, s_out = blockIdx.y, t0 = blockIdx.x * 64;
    int str = (t0 >= VLEN);
    int tid = threadIdx.x;
    int lane = tid & 31, w = tid >> 5;
    int g = lane >> 2, qi = lane & 3;

    const float* xb; int xstride;
    if (!str) {
        int f = t0 >> 10;
        xb = video + ((size_t)(b * 16 + f) * 256) * 1024 + (t0 & 1023);
        xstride = 1024;
    } else {
        xb = audio + ((size_t)b * 256) * 4096 + (t0 - VLEN);
        xstride = 4096;
    }
    // stage X: fp32 [c][t] -> bf16 [t][c]
    {
        int tx = tid & 15, cy = tid >> 4;
        for (int it = 0; it < 16; it++) {
            int c = cy + 16 * it;
            float4 v = *(const float4*)(xb + (size_t)c * xstride + tx * 4);
            int t = tx * 4;
            Xs[t + 0][c] = __float2bfloat16(v.x);
            Xs[t + 1][c] = __float2bfloat16(v.y);
            Xs[t + 2][c] = __float2bfloat16(v.z);
            Xs[t + 3][c] = __float2bfloat16(v.w);
        }
    }
    __syncthreads();

    const __nv_bfloat16* Wp = g_weffh + ((size_t)(str * 2 + b) * 768 + s_out * 256) * 256;
    float acc[4][4][4];
#pragma unroll
    for (int mt = 0; mt < 4; mt++)
#pragma unroll
        for (int nt = 0; nt < 4; nt++)
            acc[mt][nt][0] = acc[mt][nt][1] = acc[mt][nt][2] = acc[mt][nt][3] = 0.f;

#pragma unroll 4
    for (int ks = 0; ks < 16; ks++) {
        u32 a[4][4];
#pragma unroll
        for (int mt = 0; mt < 4; mt++) {
            const __nv_bfloat16* ar = &Xs[mt * 16 + g][16 * ks + 2 * qi];
            a[mt][0] = *(const u32*)ar;
            a[mt][1] = *(const u32*)(ar + 8 * 264);
            a[mt][2] = *(const u32*)(ar + 8);
            a[mt][3] = *(const u32*)(ar + 8 * 264 + 8);
        }
        u32 bb0[4], bb1[4];
#pragma unroll
        for (int nt = 0; nt < 4; nt++) {
            const __nv_bfloat16* br = Wp + (size_t)(w * 32 + nt * 8 + g) * 256 + 16 * ks + 2 * qi;
            bb0[nt] = *(const u32*)br;
            bb1[nt] = *(const u32*)(br + 8);
        }
#pragma unroll
        for (int mt = 0; mt < 4; mt++)
#pragma unroll
            for (int nt = 0; nt < 4; nt++)
                mma_bf16(acc[mt][nt], a[mt], bb0[nt], bb1[nt]);
    }

    // epilogue: +bias, pack bf16x2, store to g_qkvt[t][64ch]
    int h = w >> 1;
    int chb = (w & 1) * 32;
    const float* be = g_beff + (size_t)(str * 2 + b) * 768 + s_out * 256 + w * 32;
    size_t hbase = (((size_t)b * 3 + s_out) * 4 + h) * (size_t)Tt * 64;
    float b0v[4], b1v[4];
#pragma unroll
    for (int nt = 0; nt < 4; nt++) {
        b0v[nt] = be[nt * 8 + 2 * qi];
        b1v[nt] = be[nt * 8 + 2 * qi + 1];
    }
#pragma unroll
    for (int mt = 0; mt < 4; mt++)
#pragma unroll
        for (int nt = 0; nt < 4; nt++) {
            int t = t0 + mt * 16 + g;
            int ch = chb + nt * 8 + 2 * qi;
            *(u32*)(g_qkvt + hbase + (size_t)t * 64 + ch) =
                pack_bf16x2(acc[mt][nt][0] + b0v[nt], acc[mt][nt][1] + b1v[nt]);
            *(u32*)(g_qkvt + hbase + (size_t)(t + 8) * 64 + ch) =
                pack_bf16x2(acc[mt][nt][2] + b0v[nt], acc[mt][nt][3] + b1v[nt]);
        }
}

// ---------------- 4) mma.sync attention (FA2 style) ----------------
#define NKC     128
#define KSTRIDE 72
#define VSTRIDE 136

__global__ __launch_bounds__(256, 2) void attn_mma() {
    __shared__ __nv_bfloat16 Ks[NKC * KSTRIDE];
    __shared__ __nv_bfloat16 Vt[64 * VSTRIDE];
    int tid = threadIdx.x;
    int lane = tid & 31, w = tid >> 5;
    int g = lane >> 2, qi = lane & 3;

    int id = blockIdx.x;
    int unit, qt, nchunks, tq0, tk0;
    if (id < 1024) { unit = id >> 3; qt = id & 7; nchunks = 2; }
    else { int i2 = id - 1024; unit = i2 >> 1; qt = i2 & 1; nchunks = 8; }
    int b = unit >> 6, h = (unit >> 4) & 3, f = unit & 15;
    if (id < 1024) { tq0 = f * 1024 + qt * 128; tk0 = VLEN + f * 256; }
    else           { tq0 = VLEN + f * 256 + qt * 128; tk0 = f * 1024; }

    size_t off_q = (((size_t)b * 3 + 0) * 4 + h) * (size_t)Tt * 64;
    size_t off_k = (((size_t)b * 3 + 1) * 4 + h) * (size_t)Tt * 64;
    size_t off_v = (((size_t)b * 3 + 2) * 4 + h) * (size_t)Tt * 64;

    int qbase = tq0 + w * 16;
    u32 qa[4][4];
    {
        const __nv_bfloat16* q0 = g_qkvt + off_q + (size_t)(qbase + g) * 64;
        const __nv_bfloat16* q1 = g_qkvt + off_q + (size_t)(qbase + g + 8) * 64;
#pragma unroll
        for (int s = 0; s < 4; s++) {
            qa[s][0] = *(const u32*)(q0 + 16 * s + 2 * qi);
            qa[s][1] = *(const u32*)(q1 + 16 * s + 2 * qi);
            qa[s][2] = *(const u32*)(q0 + 16 * s + 2 * qi + 8);
            qa[s][3] = *(const u32*)(q1 + 16 * s + 2 * qi + 8);
        }
    }
    float ofr[8][4];
#pragma unroll
    for (int ct = 0; ct < 8; ct++)
        ofr[ct][0] = ofr[ct][1] = ofr[ct][2] = ofr[ct][3] = 0.f;
    float mlo_r = -1e30f, mhi_r = -1e30f, llo = 0.f, lhi = 0.f;

    for (int c = 0; c < nchunks; c++) {
        int kc = tk0 + c * NKC;
        for (int m = tid; m < NKC * 8; m += 256) {
            int key = m >> 3, j = m & 7;
            uint4 kv = *(const uint4*)(g_qkvt + off_k + (size_t)(kc + key) * 64 + j * 8);
            *(uint4*)(Ks + key * KSTRIDE + j * 8) = kv;
            uint4 vv = *(const uint4*)(g_qkvt + off_v + (size_t)(kc + key) * 64 + j * 8);
            const __nv_bfloat16* pv = (const __nv_bfloat16*)&vv;
#pragma unroll
            for (int e = 0; e < 8; e++)
                Vt[(j * 8 + e) * VSTRIDE + key] = pv[e];
        }
        __syncthreads();

        for (int sc = 0; sc < NKC / 64; sc++) {
            float cfr[8][4];
#pragma unroll
            for (int nt = 0; nt < 8; nt++) {
                cfr[nt][0] = cfr[nt][1] = cfr[nt][2] = cfr[nt][3] = 0.f;
                const __nv_bfloat16* kr = Ks + (sc * 64 + nt * 8 + g) * KSTRIDE + 2 * qi;
#pragma unroll
                for (int s = 0; s < 4; s++) {
                    u32 b0 = *(const u32*)(kr + 16 * s);
                    u32 b1 = *(const u32*)(kr + 16 * s + 8);
                    mma_bf16(cfr[nt], qa[s], b0, b1);
                }
            }
            float mlo = -1e30f, mhi = -1e30f;
#pragma unroll
            for (int nt = 0; nt < 8; nt++) {
                mlo = fmaxf(mlo, fmaxf(cfr[nt][0], cfr[nt][1]));
                mhi = fmaxf(mhi, fmaxf(cfr[nt][2], cfr[nt][3]));
            }
            mlo *= 0.125f; mhi *= 0.125f;
            mlo = fmaxf(mlo, __shfl_xor_sync(0xffffffffu, mlo, 1));
            mlo = fmaxf(mlo, __shfl_xor_sync(0xffffffffu, mlo, 2));
            mhi = fmaxf(mhi, __shfl_xor_sync(0xffffffffu, mhi, 1));
            mhi = fmaxf(mhi, __shfl_xor_sync(0xffffffffu, mhi, 2));
            float nmlo = fmaxf(mlo_r, mlo), nmhi = fmaxf(mhi_r, mhi);
            float clo = __expf(mlo_r - nmlo), chi = __expf(mhi_r - nmhi);
            mlo_r = nmlo; mhi_r = nmhi;
            llo *= clo; lhi *= chi;
#pragma unroll
            for (int ct = 0; ct < 8; ct++) {
                ofr[ct][0] *= clo; ofr[ct][1] *= clo;
                ofr[ct][2] *= chi; ofr[ct][3] *= chi;
            }
            u32 plo[8], phi[8];
#pragma unroll
            for (int nt = 0; nt < 8; nt++) {
                float p0 = __expf(cfr[nt][0] * 0.125f - nmlo);
                float p1 = __expf(cfr[nt][1] * 0.125f - nmlo);
                float p2 = __expf(cfr[nt][2] * 0.125f - nmhi);
                float p3 = __expf(cfr[nt][3] * 0.125f - nmhi);
                llo += p0 + p1; lhi += p2 + p3;
                plo[nt] = pack_bf16x2(p0, p1);
                phi[nt] = pack_bf16x2(p2, p3);
            }
#pragma unroll
            for (int s = 0; s < 4; s++) {
                u32 pa[4] = {plo[2 * s], phi[2 * s], plo[2 * s + 1], phi[2 * s + 1]};
                const __nv_bfloat16* vr = Vt + g * VSTRIDE + sc * 64 + 16 * s + 2 * qi;
#pragma unroll
                for (int ct = 0; ct < 8; ct++) {
                    u32 b0 = *(const u32*)(vr + ct * 8 * VSTRIDE);
                    u32 b1 = *(const u32*)(vr + ct * 8 * VSTRIDE + 8);
                    mma_bf16(ofr[ct], pa, b0, b1);
                }
            }
        }
        __syncthreads();
    }

    llo += __shfl_xor_sync(0xffffffffu, llo, 1);
    llo += __shfl_xor_sync(0xffffffffu, llo, 2);
    lhi += __shfl_xor_sync(0xffffffffu, lhi, 1);
    lhi += __shfl_xor_sync(0xffffffffu, lhi, 2);
    float ilo = 1.f / llo, ihi = 1.f / lhi;
    int q0 = qbase + g, q1 = qbase + g + 8;
    size_t r0 = ((size_t)b * Tt + q0) * 256;
    size_t r1 = ((size_t)b * Tt + q1) * 256;
#pragma unroll
    for (int ct = 0; ct < 8; ct++) {
        int ch = h * 64 + ct * 8 + 2 * qi;
        *(u32*)(g_attnh + r0 + ch) = pack_bf16x2(ofr[ct][0] * ilo, ofr[ct][1] * ilo);
        *(u32*)(g_attnh + r1 + ch) = pack_bf16x2(ofr[ct][2] * ihi, ofr[ct][3] * ihi);
    }
}

// ---------------- 5) proj via mma.sync (M=o, N=t) + residual ----------------
__global__ __launch_bounds__(256, 2) void proj_mma(
    const float* __restrict__ video, const float* __restrict__ audio,
    const float* __restrict__ bvp, const float* __restrict__ bap,
    float* __restrict__ out) {
    __shared__ __nv_bfloat16 Bs[64][264];   // attnT [t][c]
    int b = blockIdx.z, t0 = blockIdx.x * 64;
    int str = (t0 >= VLEN);
    int tid = threadIdx.x;
    int lane = tid & 31, w = tid >> 5;
    int g = lane >> 2, qi = lane & 3;

    // stage attnT tile: 64 rows x 512B  (FIXED: 8 uint4 per 64-elem segment)
    {
        int row = tid >> 2, seg = tid & 3;
        const uint4* src = (const uint4*)(g_attnh + ((size_t)b * Tt + t0 + row) * 256 + seg * 64);
        uint4* dst = (uint4*)&Bs[row][seg * 64];
#pragma unroll
        for (int j = 0; j < 8; j++) dst[j] = src[j];
    }
    __syncthreads();

    const __nv_bfloat16* Wp = g_wprojh + (size_t)str * 65536;
    const float* bb = str ? bap : bvp;
    int o0w = (w >> 1) * 64;
    int tw = (w & 1) * 32;

    float acc[4][4][4];
#pragma unroll
    for (int mt = 0; mt < 4; mt++)
#pragma unroll
        for (int nt = 0; nt < 4; nt++)
            acc[mt][nt][0] = acc[mt][nt][1] = acc[mt][nt][2] = acc[mt][nt][3] = 0.f;

#pragma unroll 4
    for (int ks = 0; ks < 16; ks++) {
        u32 a[4][4];
#pragma unroll
        for (int mt = 0; mt < 4; mt++) {
            const __nv_bfloat16* ar = Wp + (size_t)(o0w + mt * 16 + g) * 256 + 16 * ks + 2 * qi;
            a[mt][0] = *(const u32*)ar;
            a[mt][1] = *(const u32*)(ar + 8 * 256);
            a[mt][2] = *(const u32*)(ar + 8);
            a[mt][3] = *(const u32*)(ar + 8 * 256 + 8);
        }
        u32 bb0[4], bb1[4];
#pragma unroll
        for (int nt = 0; nt < 4; nt++) {
            const __nv_bfloat16* br = &Bs[tw + nt * 8 + g][16 * ks + 2 * qi];
            bb0[nt] = *(const u32*)br;
            bb1[nt] = *(const u32*)(br + 8);
        }
#pragma unroll
        for (int mt = 0; mt < 4; mt++)
#pragma unroll
            for (int nt = 0; nt < 4; nt++)
                mma_bf16(acc[mt][nt], a[mt], bb0[nt], bb1[nt]);
    }

    // epilogue: bias + residual, fp32 out
#pragma unroll
    for (int mt = 0; mt < 4; mt++) {
        int o_lo = o0w + mt * 16 + g;
        int o_hi = o_lo + 8;
        float be_lo = bb[o_lo], be_hi = bb[o_hi];
#pragma unroll
        for (int nt = 0; nt < 4; nt++) {
            int t = tw + nt * 8 + 2 * qi;
            if (!str) {
                int f = t0 >> 10;
                size_t base = ((size_t)(b * 16 + f) * 256) * 1024 + (t0 & 1023) + t;
                size_t a_lo = base + (size_t)o_lo * 1024;
                size_t a_hi = base + (size_t)o_hi * 1024;
                float2 r = *(const float2*)(video + a_lo);
                r.x += acc[mt][nt][0] + be_lo; r.y += acc[mt][nt][1] + be_lo;
                *(float2*)(out + a_lo) = r;
                float2 r2 = *(const float2*)(video + a_hi);
                r2.x += acc[mt][nt][2] + be_hi; r2.y += acc[mt][nt][3] + be_hi;
                *(float2*)(out + a_hi) = r2;
            } else {
                size_t base = ((size_t)b * 256) * 4096 + (t0 - VLEN) + t;
                size_t a_lo = base + (size_t)o_lo * 4096;
                size_t a_hi = base + (size_t)o_hi * 4096;
                float2 r = *(const float2*)(audio + a_lo);
                r.x += acc[mt][nt][0] + be_lo; r.y += acc[mt][nt][1] + be_lo;
                *(float2*)(out + 8388608 + a_lo) = r;
                float2 r2 = *(const float2*)(audio + a_hi);
                r2.x += acc[mt][nt][2] + be_hi; r2.y += acc[mt][nt][3] + be_hi;
                *(float2*)(out + 8388608 + a_hi) = r2;
            }
        }
    }
}

// ---------------- launch ----------------
extern "C" void kernel_launch(void* const* d_in, const int* in_sizes, int n_in,
                              void* d_out, int out_size) {
    const float* video  = (const float*)d_in[0];
    const float* audio  = (const float*)d_in[1];
    const float* gvs    = (const float*)d_in[2];
    const float* gvb    = (const float*)d_in[3];
    const float* gas    = (const float*)d_in[4];
    const float* gab    = (const float*)d_in[5];
    const float* w_vqkv = (const float*)d_in[6];
    const float* b_vqkv = (const float*)d_in[7];
    const float* w_aqkv = (const float*)d_in[8];
    const float* b_aqkv = (const float*)d_in[9];
    const float* w_vproj = (const float*)d_in[10];
    const float* b_vproj = (const float*)d_in[11];
    const float* w_aproj = (const float*)d_in[12];
    const float* b_aproj = (const float*)d_in[13];
    float* out = (float*)d_out;

    stats_kernel<<<128, 256>>>(video, audio);
    fold_kernel<<<3072, 256>>>(w_vqkv, b_vqkv, w_aqkv, b_aqkv, gvs, gvb, gas, gab);
    wconv_kernel<<<256, 256>>>(w_vproj, w_aproj);
    dim3 gq(320, 3, 2);
    qkv_mma<<<gq, 256>>>(video, audio);
    attn_mma<<<1280, 256>>>();
    dim3 gp(320, 1, 2);
    proj_mma<<<gp, 256>>>(video, audio, b_vproj, b_aproj, out);
}

// round 8
// speedup vs baseline: 5.1291x; 1.1158x over previous
#include <cuda_runtime.h>
#include <cuda_bf16.h>
#include <cstdint>

// Problem constants: B=2, F=16, C=256, H=W=32, L=4096, NH=4, ch=64
#define Tt   20480        // vlen + L
#define VLEN 16384        // F * H * W

typedef unsigned long long u64;
typedef unsigned int u32;

// ---------------- static device scratch (no allocations) ----------------
__device__ float g_stats[256];                 // [s][b][g][{mu,rstd}]
__device__ __nv_bfloat16 g_weffh[4 * 768 * 256];  // folded GN*W per (s,b), bf16
__device__ float g_beff[4 * 768];              // folded bias per (s,b)
__device__ __nv_bfloat16 g_wprojh[2 * 256 * 256]; // proj weights bf16 [str][o][c]
__device__ __nv_bfloat16 g_qkvt[31457280];     // [b][{q,k,v}][h][t][64ch]  (63MB)
__device__ __nv_bfloat16 g_attnh[10485760];    // [b][t][256c]  (21MB)

// ---------------- mma.sync bf16 helper ----------------
__device__ __forceinline__ void mma_bf16(float* c, const u32* a, u32 b0, u32 b1) {
    asm volatile("mma.sync.aligned.m16n8k16.row.col.f32.bf16.bf16.f32 "
        "{%0,%1,%2,%3}, {%4,%5,%6,%7}, {%8,%9}, {%0,%1,%2,%3};"
        : "+f"(c[0]), "+f"(c[1]), "+f"(c[2]), "+f"(c[3])
        : "r"(a[0]), "r"(a[1]), "r"(a[2]), "r"(a[3]), "r"(b0), "r"(b1));
}
__device__ __forceinline__ u32 pack_bf16x2(float lo, float hi) {
    __nv_bfloat162 v = __floats2bfloat162_rn(lo, hi);
    return *(u32*)&v;
}

// ---------------- 1) GroupNorm stats ----------------
__global__ __launch_bounds__(256) void stats_kernel(const float* __restrict__ video,
                                                    const float* __restrict__ audio) {
    int id = blockIdx.x;
    int s = id >> 6, rem = id & 63, b = rem >> 5, g = rem & 31;
    int tid = threadIdx.x;
    float sum = 0.f, sq = 0.f;
    if (s == 0) {
        const float* base = video + ((size_t)(b * 16) * 256 + g * 8) * 1024;
        for (int i = tid; i < 32768; i += 256) {
            int j = i * 4;
            int f = j >> 13, c = (j >> 10) & 7, hw = j & 1023;
            float4 v = *(const float4*)(base + (size_t)f * 262144 + c * 1024 + hw);
            sum += v.x + v.y + v.z + v.w;
            sq  += v.x * v.x + v.y * v.y + v.z * v.z + v.w * v.w;
        }
    } else {
        const float* base = audio + ((size_t)b * 256 + g * 8) * 4096;
        for (int i = tid; i < 8192; i += 256) {
            int j = i * 4;
            int c = j >> 12, t = j & 4095;
            float4 v = *(const float4*)(base + (size_t)c * 4096 + t);
            sum += v.x + v.y + v.z + v.w;
            sq  += v.x * v.x + v.y * v.y + v.z * v.z + v.w * v.w;
        }
    }
    for (int o = 16; o; o >>= 1) {
        sum += __shfl_xor_sync(0xffffffffu, sum, o);
        sq  += __shfl_xor_sync(0xffffffffu, sq, o);
    }
    __shared__ float ss[8], sqq[8];
    int w = tid >> 5;
    if ((tid & 31) == 0) { ss[w] = sum; sqq[w] = sq; }
    __syncthreads();
    if (tid == 0) {
        float S1 = 0.f, S2 = 0.f;
        for (int i = 0; i < 8; i++) { S1 += ss[i]; S2 += sqq[i]; }
        float N = (s == 0) ? 131072.f : 32768.f;
        float mu = S1 / N;
        float var = S2 / N - mu * mu;
        int idx = ((s * 2 + b) * 32 + g) * 2;
        g_stats[idx] = mu;
        g_stats[idx + 1] = rsqrtf(var + 1e-5f);
    }
}

// ---------------- 2) fold GN affine into QKV weights (bf16 out) ----------------
__global__ __launch_bounds__(256) void fold_kernel(
    const float* __restrict__ wv, const float* __restrict__ bv,
    const float* __restrict__ wa, const float* __restrict__ ba,
    const float* __restrict__ gvs, const float* __restrict__ gvb,
    const float* __restrict__ gas, const float* __restrict__ gab) {
    int bid = blockIdx.x;
    int s = bid / 1536;
    int r = bid % 1536;
    int b = r / 768;
    int o = r % 768;
    int c = threadIdx.x;
    const float* W  = s ? wa  : wv;
    const float* Bb = s ? ba  : bv;
    const float* sc = s ? gas : gvs;
    const float* bi = s ? gab : gvb;
    int g = c >> 3;
    int sb = ((s * 2 + b) * 32 + g) * 2;
    float mu = g_stats[sb], rs = g_stats[sb + 1];
    float alpha = sc[c] * rs;
    float beta = bi[c] - mu * alpha;
    float w = W[(size_t)o * 256 + c];
    g_weffh[((size_t)(s * 2 + b) * 768 + o) * 256 + c] = __float2bfloat16(w * alpha);
    float part = w * beta;
    for (int off = 16; off; off >>= 1) part += __shfl_xor_sync(0xffffffffu, part, off);
    __shared__ float red[8];
    if ((c & 31) == 0) red[c >> 5] = part;
    __syncthreads();
    if (c == 0) {
        float tot = Bb[o];
        for (int i = 0; i < 8; i++) tot += red[i];
        g_beff[(size_t)(s * 2 + b) * 768 + o] = tot;
    }
}

// ---------------- 2b) convert proj weights to bf16 ----------------
__global__ __launch_bounds__(256) void wconv_kernel(const float* __restrict__ wvp,
                                                    const float* __restrict__ wap) {
    int i = blockIdx.x * 256 + threadIdx.x;   // grid 256 -> 65536
    g_wprojh[i] = __float2bfloat16(wvp[i]);
    g_wprojh[65536 + i] = __float2bfloat16(wap[i]);
}

// ---------------- 3) QKV GEMM via mma.sync: C = X^T @ W^T  (M=t, N=o) ----------------
// grid (320, 3, 2). Weights staged through smem in 16-c chunks with register
// prefetch (kills the scattered-LDG L1 amplification).
#define WCH 24   // smem stride for 16-col weight chunk (conflict-free: g*12%32 distinct)

__global__ __launch_bounds__(256, 2) void qkv_mma(const float* __restrict__ video,
                                                  const float* __restrict__ audio) {
    __shared__ __align__(16) __nv_bfloat16 Xs[64 * 264];
    __shared__ __align__(16) __nv_bfloat16 Ws[256 * WCH];
    int b = blockIdx.z, s_out = blockIdx.y, t0 = blockIdx.x * 64;
    int str = (t0 >= VLEN);
    int tid = threadIdx.x;
    int lane = tid & 31, w = tid >> 5;
    int g = lane >> 2, qi = lane & 3;

    const float* xb; int xstride;
    if (!str) {
        int f = t0 >> 10;
        xb = video + ((size_t)(b * 16 + f) * 256) * 1024 + (t0 & 1023);
        xstride = 1024;
    } else {
        xb = audio + ((size_t)b * 256) * 4096 + (t0 - VLEN);
        xstride = 4096;
    }
    // stage X: fp32 [c][t] -> bf16 [t][c]
    {
        int tx = tid & 15, cy = tid >> 4;
        for (int it = 0; it < 16; it++) {
            int c = cy + 16 * it;
            float4 v = *(const float4*)(xb + (size_t)c * xstride + tx * 4);
            int t = tx * 4;
            Xs[(t + 0) * 264 + c] = __float2bfloat16(v.x);
            Xs[(t + 1) * 264 + c] = __float2bfloat16(v.y);
            Xs[(t + 2) * 264 + c] = __float2bfloat16(v.z);
            Xs[(t + 3) * 264 + c] = __float2bfloat16(v.w);
        }
    }
    const __nv_bfloat16* Wp = g_weffh + ((size_t)(str * 2 + b) * 768 + s_out * 256) * 256;
    // prefetch chunk 0 (rows o, cols 0..15): idx -> row=idx>>1, half=idx&1
    uint4 wpre[2];
#pragma unroll
    for (int r = 0; r < 2; r++) {
        int idx = tid + 256 * r;
        wpre[r] = *(const uint4*)(Wp + (size_t)(idx >> 1) * 256 + (idx & 1) * 8);
    }
    float acc[4][4][4];
#pragma unroll
    for (int mt = 0; mt < 4; mt++)
#pragma unroll
        for (int nt = 0; nt < 4; nt++)
            acc[mt][nt][0] = acc[mt][nt][1] = acc[mt][nt][2] = acc[mt][nt][3] = 0.f;

    for (int kc = 0; kc < 16; kc++) {
#pragma unroll
        for (int r = 0; r < 2; r++) {
            int idx = tid + 256 * r;
            *(uint4*)(Ws + (idx >> 1) * WCH + (idx & 1) * 8) = wpre[r];
        }
        __syncthreads();
        if (kc < 15) {
#pragma unroll
            for (int r = 0; r < 2; r++) {
                int idx = tid + 256 * r;
                wpre[r] = *(const uint4*)(Wp + (size_t)(idx >> 1) * 256 + (kc + 1) * 16 + (idx & 1) * 8);
            }
        }
        u32 a[4][4];
#pragma unroll
        for (int mt = 0; mt < 4; mt++) {
            const __nv_bfloat16* ar = Xs + (mt * 16 + g) * 264 + kc * 16 + 2 * qi;
            a[mt][0] = *(const u32*)ar;
            a[mt][1] = *(const u32*)(ar + 8 * 264);
            a[mt][2] = *(const u32*)(ar + 8);
            a[mt][3] = *(const u32*)(ar + 8 * 264 + 8);
        }
        u32 bb0[4], bb1[4];
#pragma unroll
        for (int nt = 0; nt < 4; nt++) {
            const __nv_bfloat16* br = Ws + (w * 32 + nt * 8 + g) * WCH + 2 * qi;
            bb0[nt] = *(const u32*)br;
            bb1[nt] = *(const u32*)(br + 8);
        }
#pragma unroll
        for (int mt = 0; mt < 4; mt++)
#pragma unroll
            for (int nt = 0; nt < 4; nt++)
                mma_bf16(acc[mt][nt], a[mt], bb0[nt], bb1[nt]);
        __syncthreads();
    }

    // epilogue: +bias, pack bf16x2, store to g_qkvt[t][64ch]
    int h = w >> 1;
    int chb = (w & 1) * 32;
    const float* be = g_beff + (size_t)(str * 2 + b) * 768 + s_out * 256 + w * 32;
    size_t hbase = (((size_t)b * 3 + s_out) * 4 + h) * (size_t)Tt * 64;
    float b0v[4], b1v[4];
#pragma unroll
    for (int nt = 0; nt < 4; nt++) {
        b0v[nt] = be[nt * 8 + 2 * qi];
        b1v[nt] = be[nt * 8 + 2 * qi + 1];
    }
#pragma unroll
    for (int mt = 0; mt < 4; mt++)
#pragma unroll
        for (int nt = 0; nt < 4; nt++) {
            int t = t0 + mt * 16 + g;
            int ch = chb + nt * 8 + 2 * qi;
            *(u32*)(g_qkvt + hbase + (size_t)t * 64 + ch) =
                pack_bf16x2(acc[mt][nt][0] + b0v[nt], acc[mt][nt][1] + b1v[nt]);
            *(u32*)(g_qkvt + hbase + (size_t)(t + 8) * 64 + ch) =
                pack_bf16x2(acc[mt][nt][2] + b0v[nt], acc[mt][nt][3] + b1v[nt]);
        }
}

// ---------------- 4) mma.sync attention (FA2 style, ldmatrix.trans for V) ----------------
#define NKC     128
#define KSTRIDE 72

__global__ __launch_bounds__(256, 2) void attn_mma() {
    __shared__ __align__(16) __nv_bfloat16 Ks[NKC * KSTRIDE];
    __shared__ __align__(16) __nv_bfloat16 Vs[NKC * KSTRIDE];   // [key][ch], like Ks
    int tid = threadIdx.x;
    int lane = tid & 31, w = tid >> 5;
    int g = lane >> 2, qi = lane & 3;

    int id = blockIdx.x;
    int unit, qt, nchunks, tq0, tk0;
    if (id < 1024) { unit = id >> 3; qt = id & 7; nchunks = 2; }
    else { int i2 = id - 1024; unit = i2 >> 1; qt = i2 & 1; nchunks = 8; }
    int b = unit >> 6, h = (unit >> 4) & 3, f = unit & 15;
    if (id < 1024) { tq0 = f * 1024 + qt * 128; tk0 = VLEN + f * 256; }
    else           { tq0 = VLEN + f * 256 + qt * 128; tk0 = f * 1024; }

    size_t off_q = (((size_t)b * 3 + 0) * 4 + h) * (size_t)Tt * 64;
    size_t off_k = (((size_t)b * 3 + 1) * 4 + h) * (size_t)Tt * 64;
    size_t off_v = (((size_t)b * 3 + 2) * 4 + h) * (size_t)Tt * 64;

    int qbase = tq0 + w * 16;
    u32 qa[4][4];
    {
        const __nv_bfloat16* q0 = g_qkvt + off_q + (size_t)(qbase + g) * 64;
        const __nv_bfloat16* q1 = g_qkvt + off_q + (size_t)(qbase + g + 8) * 64;
#pragma unroll
        for (int s = 0; s < 4; s++) {
            qa[s][0] = *(const u32*)(q0 + 16 * s + 2 * qi);
            qa[s][1] = *(const u32*)(q1 + 16 * s + 2 * qi);
            qa[s][2] = *(const u32*)(q0 + 16 * s + 2 * qi + 8);
            qa[s][3] = *(const u32*)(q1 + 16 * s + 2 * qi + 8);
        }
    }
    // per-lane ldmatrix.trans base: rows = keys (lane&15), cols = (lane>>4)*8
    u32 vlane = (u32)__cvta_generic_to_shared(Vs)
              + (u32)(((lane & 15) * KSTRIDE + (lane >> 4) * 8) * 2);

    float ofr[8][4];
#pragma unroll
    for (int ct = 0; ct < 8; ct++)
        ofr[ct][0] = ofr[ct][1] = ofr[ct][2] = ofr[ct][3] = 0.f;
    float mlo_r = -1e30f, mhi_r = -1e30f, llo = 0.f, lhi = 0.f;

    for (int c = 0; c < nchunks; c++) {
        int kc = tk0 + c * NKC;
        for (int m = tid; m < NKC * 8; m += 256) {
            int key = m >> 3, j = m & 7;
            *(uint4*)(Ks + key * KSTRIDE + j * 8) =
                *(const uint4*)(g_qkvt + off_k + (size_t)(kc + key) * 64 + j * 8);
            *(uint4*)(Vs + key * KSTRIDE + j * 8) =
                *(const uint4*)(g_qkvt + off_v + (size_t)(kc + key) * 64 + j * 8);
        }
        __syncthreads();

        for (int sc = 0; sc < NKC / 64; sc++) {
            float cfr[8][4];
#pragma unroll
            for (int nt = 0; nt < 8; nt++) {
                cfr[nt][0] = cfr[nt][1] = cfr[nt][2] = cfr[nt][3] = 0.f;
                const __nv_bfloat16* kr = Ks + (sc * 64 + nt * 8 + g) * KSTRIDE + 2 * qi;
#pragma unroll
                for (int s = 0; s < 4; s++) {
                    u32 b0 = *(const u32*)(kr + 16 * s);
                    u32 b1 = *(const u32*)(kr + 16 * s + 8);
                    mma_bf16(cfr[nt], qa[s], b0, b1);
                }
            }
            float mlo = -1e30f, mhi = -1e30f;
#pragma unroll
            for (int nt = 0; nt < 8; nt++) {
                mlo = fmaxf(mlo, fmaxf(cfr[nt][0], cfr[nt][1]));
                mhi = fmaxf(mhi, fmaxf(cfr[nt][2], cfr[nt][3]));
            }
            mlo *= 0.125f; mhi *= 0.125f;
            mlo = fmaxf(mlo, __shfl_xor_sync(0xffffffffu, mlo, 1));
            mlo = fmaxf(mlo, __shfl_xor_sync(0xffffffffu, mlo, 2));
            mhi = fmaxf(mhi, __shfl_xor_sync(0xffffffffu, mhi, 1));
            mhi = fmaxf(mhi, __shfl_xor_sync(0xffffffffu, mhi, 2));
            float nmlo = fmaxf(mlo_r, mlo), nmhi = fmaxf(mhi_r, mhi);
            float clo = __expf(mlo_r - nmlo), chi = __expf(mhi_r - nmhi);
            mlo_r = nmlo; mhi_r = nmhi;
            llo *= clo; lhi *= chi;
#pragma unroll
            for (int ct = 0; ct < 8; ct++) {
                ofr[ct][0] *= clo; ofr[ct][1] *= clo;
                ofr[ct][2] *= chi; ofr[ct][3] *= chi;
            }
            u32 plo[8], phi[8];
#pragma unroll
            for (int nt = 0; nt < 8; nt++) {
                float p0 = __expf(cfr[nt][0] * 0.125f - nmlo);
                float p1 = __expf(cfr[nt][1] * 0.125f - nmlo);
                float p2 = __expf(cfr[nt][2] * 0.125f - nmhi);
                float p3 = __expf(cfr[nt][3] * 0.125f - nmhi);
                llo += p0 + p1; lhi += p2 + p3;
                plo[nt] = pack_bf16x2(p0, p1);
                phi[nt] = pack_bf16x2(p2, p3);
            }
#pragma unroll
            for (int s = 0; s < 4; s++) {
                u32 pa[4] = {plo[2 * s], phi[2 * s], plo[2 * s + 1], phi[2 * s + 1]};
                u32 vrow = vlane + (u32)((sc * 64 + 16 * s) * KSTRIDE * 2);
#pragma unroll
                for (int ctp = 0; ctp < 4; ctp++) {
                    u32 r0, r1, r2, r3;
                    asm volatile("ldmatrix.sync.aligned.m8n8.x4.trans.shared.b16 "
                        "{%0,%1,%2,%3}, [%4];"
                        : "=r"(r0), "=r"(r1), "=r"(r2), "=r"(r3)
                        : "r"(vrow + ctp * 32));
                    mma_bf16(ofr[2 * ctp], pa, r0, r1);
                    mma_bf16(ofr[2 * ctp + 1], pa, r2, r3);
                }
            }
        }
        __syncthreads();
    }

    llo += __shfl_xor_sync(0xffffffffu, llo, 1);
    llo += __shfl_xor_sync(0xffffffffu, llo, 2);
    lhi += __shfl_xor_sync(0xffffffffu, lhi, 1);
    lhi += __shfl_xor_sync(0xffffffffu, lhi, 2);
    float ilo = 1.f / llo, ihi = 1.f / lhi;
    int q0 = qbase + g, q1 = qbase + g + 8;
    size_t r0 = ((size_t)b * Tt + q0) * 256;
    size_t r1 = ((size_t)b * Tt + q1) * 256;
#pragma unroll
    for (int ct = 0; ct < 8; ct++) {
        int ch = h * 64 + ct * 8 + 2 * qi;
        *(u32*)(g_attnh + r0 + ch) = pack_bf16x2(ofr[ct][0] * ilo, ofr[ct][1] * ilo);
        *(u32*)(g_attnh + r1 + ch) = pack_bf16x2(ofr[ct][2] * ihi, ofr[ct][3] * ihi);
    }
}

// ---------------- 5) proj via mma.sync (M=o, N=t) + residual ----------------
__global__ __launch_bounds__(256, 2) void proj_mma(
    const float* __restrict__ video, const float* __restrict__ audio,
    const float* __restrict__ bvp, const float* __restrict__ bap,
    float* __restrict__ out) {
    __shared__ __align__(16) __nv_bfloat16 Bs[64 * 264];    // attnT [t][c]
    __shared__ __align__(16) __nv_bfloat16 Wsm[256 * WCH];
    int b = blockIdx.z, t0 = blockIdx.x * 64;
    int str = (t0 >= VLEN);
    int tid = threadIdx.x;
    int lane = tid & 31, w = tid >> 5;
    int g = lane >> 2, qi = lane & 3;

    // stage attnT tile: 64 rows x 512B
    {
        int row = tid >> 2, seg = tid & 3;
        const uint4* src = (const uint4*)(g_attnh + ((size_t)b * Tt + t0 + row) * 256 + seg * 64);
        uint4* dst = (uint4*)(Bs + row * 264 + seg * 64);
#pragma unroll
        for (int j = 0; j < 8; j++) dst[j] = src[j];
    }
    const __nv_bfloat16* Wp = g_wprojh + (size_t)str * 65536;
    const float* bb = str ? bap : bvp;
    uint4 wpre[2];
#pragma unroll
    for (int r = 0; r < 2; r++) {
        int idx = tid + 256 * r;
        wpre[r] = *(const uint4*)(Wp + (size_t)(idx >> 1) * 256 + (idx & 1) * 8);
    }
    int o0w = (w >> 1) * 64;
    int tw = (w & 1) * 32;

    float acc[4][4][4];
#pragma unroll
    for (int mt = 0; mt < 4; mt++)
#pragma unroll
        for (int nt = 0; nt < 4; nt++)
            acc[mt][nt][0] = acc[mt][nt][1] = acc[mt][nt][2] = acc[mt][nt][3] = 0.f;

    for (int kc = 0; kc < 16; kc++) {
#pragma unroll
        for (int r = 0; r < 2; r++) {
            int idx = tid + 256 * r;
            *(uint4*)(Wsm + (idx >> 1) * WCH + (idx & 1) * 8) = wpre[r];
        }
        __syncthreads();
        if (kc < 15) {
#pragma unroll
            for (int r = 0; r < 2; r++) {
                int idx = tid + 256 * r;
                wpre[r] = *(const uint4*)(Wp + (size_t)(idx >> 1) * 256 + (kc + 1) * 16 + (idx & 1) * 8);
            }
        }
        u32 a[4][4];
#pragma unroll
        for (int mt = 0; mt < 4; mt++) {
            const __nv_bfloat16* ar = Wsm + (o0w + mt * 16 + g) * WCH + 2 * qi;
            a[mt][0] = *(const u32*)ar;
            a[mt][1] = *(const u32*)(ar + 8 * WCH);
            a[mt][2] = *(const u32*)(ar + 8);
            a[mt][3] = *(const u32*)(ar + 8 * WCH + 8);
        }
        u32 bb0[4], bb1[4];
#pragma unroll
        for (int nt = 0; nt < 4; nt++) {
            const __nv_bfloat16* br = Bs + (tw + nt * 8 + g) * 264 + kc * 16 + 2 * qi;
            bb0[nt] = *(const u32*)br;
            bb1[nt] = *(const u32*)(br + 8);
        }
#pragma unroll
        for (int mt = 0; mt < 4; mt++)
#pragma unroll
            for (int nt = 0; nt < 4; nt++)
                mma_bf16(acc[mt][nt], a[mt], bb0[nt], bb1[nt]);
        __syncthreads();
    }

    // epilogue: bias + residual, fp32 out
#pragma unroll
    for (int mt = 0; mt < 4; mt++) {
        int o_lo = o0w + mt * 16 + g;
        int o_hi = o_lo + 8;
        float be_lo = bb[o_lo], be_hi = bb[o_hi];
#pragma unroll
        for (int nt = 0; nt < 4; nt++) {
            int t = tw + nt * 8 + 2 * qi;
            if (!str) {
                int f = t0 >> 10;
                size_t base = ((size_t)(b * 16 + f) * 256) * 1024 + (t0 & 1023) + t;
                size_t a_lo = base + (size_t)o_lo * 1024;
                size_t a_hi = base + (size_t)o_hi * 1024;
                float2 r = *(const float2*)(video + a_lo);
                r.x += acc[mt][nt][0] + be_lo; r.y += acc[mt][nt][1] + be_lo;
                *(float2*)(out + a_lo) = r;
                float2 r2 = *(const float2*)(video + a_hi);
                r2.x += acc[mt][nt][2] + be_hi; r2.y += acc[mt][nt][3] + be_hi;
                *(float2*)(out + a_hi) = r2;
            } else {
                size_t base = ((size_t)b * 256) * 4096 + (t0 - VLEN) + t;
                size_t a_lo = base + (size_t)o_lo * 4096;
                size_t a_hi = base + (size_t)o_hi * 4096;
                float2 r = *(const float2*)(audio + a_lo);
                r.x += acc[mt][nt][0] + be_lo; r.y += acc[mt][nt][1] + be_lo;
                *(float2*)(out + 8388608 + a_lo) = r;
                float2 r2 = *(const float2*)(audio + a_hi);
                r2.x += acc[mt][nt][2] + be_hi; r2.y += acc[mt][nt][3] + be_hi;
                *(float2*)(out + 8388608 + a_hi) = r2;
            }
        }
    }
}

// ---------------- launch ----------------
extern "C" void kernel_launch(void* const* d_in, const int* in_sizes, int n_in,
                              void* d_out, int out_size) {
    const float* video  = (const float*)d_in[0];
    const float* audio  = (const float*)d_in[1];
    const float* gvs    = (const float*)d_in[2];
    const float* gvb    = (const float*)d_in[3];
    const float* gas    = (const float*)d_in[4];
    const float* gab    = (const float*)d_in[5];
    const float* w_vqkv = (const float*)d_in[6];
    const float* b_vqkv = (const float*)d_in[7];
    const float* w_aqkv = (const float*)d_in[8];
    const float* b_aqkv = (const float*)d_in[9];
    const float* w_vproj = (const float*)d_in[10];
    const float* b_vproj = (const float*)d_in[11];
    const float* w_aproj = (const float*)d_in[12];
    const float* b_aproj = (const float*)d_in[13];
    float* out = (float*)d_out;

    stats_kernel<<<128, 256>>>(video, audio);
    fold_kernel<<<3072, 256>>>(w_vqkv, b_vqkv, w_aqkv, b_aqkv, gvs, gvb, gas, gab);
    wconv_kernel<<<256, 256>>>(w_vproj, w_aproj);
    dim3 gq(320, 3, 2);
    qkv_mma<<<gq, 256>>>(video, audio);
    attn_mma<<<1280, 256>>>();
    dim3 gp(320, 1, 2);
    proj_mma<<<gp, 256>>>(video, audio, b_vproj, b_aproj, out);
}

// round 9
// speedup vs baseline: 5.5231x; 1.0768x over previous
#include <cuda_runtime.h>
#include <cuda_bf16.h>
#include <cstdint>

// Problem constants: B=2, F=16, C=256, H=W=32, L=4096, NH=4, ch=64
#define Tt   20480        // vlen + L
#define VLEN 16384        // F * H * W

typedef unsigned long long u64;
typedef unsigned int u32;

// ---------------- static device scratch (no allocations) ----------------
__device__ float g_stats[256];                 // [s][b][g][{mu,rstd}]
__device__ __nv_bfloat16 g_weffh[4 * 768 * 256];  // folded GN*W per (s,b), bf16
__device__ float g_beff[4 * 768];              // folded bias per (s,b)
__device__ __nv_bfloat16 g_wprojh[2 * 256 * 256]; // proj weights bf16 [str][o][c]
__device__ __nv_bfloat16 g_qkvt[31457280];     // [b][{q,k,v}][h][t][64ch]  (63MB)
__device__ __nv_bfloat16 g_attnh[10485760];    // [b][t][256c]  (21MB)

// ---------------- mma.sync bf16 helper ----------------
__device__ __forceinline__ void mma_bf16(float* c, const u32* a, u32 b0, u32 b1) {
    asm volatile("mma.sync.aligned.m16n8k16.row.col.f32.bf16.bf16.f32 "
        "{%0,%1,%2,%3}, {%4,%5,%6,%7}, {%8,%9}, {%0,%1,%2,%3};"
        : "+f"(c[0]), "+f"(c[1]), "+f"(c[2]), "+f"(c[3])
        : "r"(a[0]), "r"(a[1]), "r"(a[2]), "r"(a[3]), "r"(b0), "r"(b1));
}
__device__ __forceinline__ u32 pack_bf16x2(float lo, float hi) {
    __nv_bfloat162 v = __floats2bfloat162_rn(lo, hi);
    return *(u32*)&v;
}
__device__ __forceinline__ void ldmx4(u32& r0, u32& r1, u32& r2, u32& r3, u32 addr) {
    asm volatile("ldmatrix.sync.aligned.m8n8.x4.shared.b16 {%0,%1,%2,%3}, [%4];"
        : "=r"(r0), "=r"(r1), "=r"(r2), "=r"(r3) : "r"(addr));
}
__device__ __forceinline__ void ldmx4t(u32& r0, u32& r1, u32& r2, u32& r3, u32 addr) {
    asm volatile("ldmatrix.sync.aligned.m8n8.x4.trans.shared.b16 {%0,%1,%2,%3}, [%4];"
        : "=r"(r0), "=r"(r1), "=r"(r2), "=r"(r3) : "r"(addr));
}

// ---------------- 1) GroupNorm stats ----------------
__global__ __launch_bounds__(256) void stats_kernel(const float* __restrict__ video,
                                                    const float* __restrict__ audio) {
    int id = blockIdx.x;
    int s = id >> 6, rem = id & 63, b = rem >> 5, g = rem & 31;
    int tid = threadIdx.x;
    float sum = 0.f, sq = 0.f;
    if (s == 0) {
        const float* base = video + ((size_t)(b * 16) * 256 + g * 8) * 1024;
        for (int i = tid; i < 32768; i += 256) {
            int j = i * 4;
            int f = j >> 13, c = (j >> 10) & 7, hw = j & 1023;
            float4 v = *(const float4*)(base + (size_t)f * 262144 + c * 1024 + hw);
            sum += v.x + v.y + v.z + v.w;
            sq  += v.x * v.x + v.y * v.y + v.z * v.z + v.w * v.w;
        }
    } else {
        const float* base = audio + ((size_t)b * 256 + g * 8) * 4096;
        for (int i = tid; i < 8192; i += 256) {
            int j = i * 4;
            int c = j >> 12, t = j & 4095;
            float4 v = *(const float4*)(base + (size_t)c * 4096 + t);
            sum += v.x + v.y + v.z + v.w;
            sq  += v.x * v.x + v.y * v.y + v.z * v.z + v.w * v.w;
        }
    }
    for (int o = 16; o; o >>= 1) {
        sum += __shfl_xor_sync(0xffffffffu, sum, o);
        sq  += __shfl_xor_sync(0xffffffffu, sq, o);
    }
    __shared__ float ss[8], sqq[8];
    int w = tid >> 5;
    if ((tid & 31) == 0) { ss[w] = sum; sqq[w] = sq; }
    __syncthreads();
    if (tid == 0) {
        float S1 = 0.f, S2 = 0.f;
        for (int i = 0; i < 8; i++) { S1 += ss[i]; S2 += sqq[i]; }
        float N = (s == 0) ? 131072.f : 32768.f;
        float mu = S1 / N;
        float var = S2 / N - mu * mu;
        int idx = ((s * 2 + b) * 32 + g) * 2;
        g_stats[idx] = mu;
        g_stats[idx + 1] = rsqrtf(var + 1e-5f);
    }
}

// ---------------- 2) fold GN affine into QKV weights (bf16 out) ----------------
__global__ __launch_bounds__(256) void fold_kernel(
    const float* __restrict__ wv, const float* __restrict__ bv,
    const float* __restrict__ wa, const float* __restrict__ ba,
    const float* __restrict__ gvs, const float* __restrict__ gvb,
    const float* __restrict__ gas, const float* __restrict__ gab) {
    int bid = blockIdx.x;
    int s = bid / 1536;
    int r = bid % 1536;
    int b = r / 768;
    int o = r % 768;
    int c = threadIdx.x;
    const float* W  = s ? wa  : wv;
    const float* Bb = s ? ba  : bv;
    const float* sc = s ? gas : gvs;
    const float* bi = s ? gab : gvb;
    int g = c >> 3;
    int sb = ((s * 2 + b) * 32 + g) * 2;
    float mu = g_stats[sb], rs = g_stats[sb + 1];
    float alpha = sc[c] * rs;
    float beta = bi[c] - mu * alpha;
    float w = W[(size_t)o * 256 + c];
    g_weffh[((size_t)(s * 2 + b) * 768 + o) * 256 + c] = __float2bfloat16(w * alpha);
    float part = w * beta;
    for (int off = 16; off; off >>= 1) part += __shfl_xor_sync(0xffffffffu, part, off);
    __shared__ float red[8];
    if ((c & 31) == 0) red[c >> 5] = part;
    __syncthreads();
    if (c == 0) {
        float tot = Bb[o];
        for (int i = 0; i < 8; i++) tot += red[i];
        g_beff[(size_t)(s * 2 + b) * 768 + o] = tot;
    }
}

// ---------------- 2b) convert proj weights to bf16 ----------------
__global__ __launch_bounds__(256) void wconv_kernel(const float* __restrict__ wvp,
                                                    const float* __restrict__ wap) {
    int i = blockIdx.x * 256 + threadIdx.x;   // grid 256 -> 65536
    g_wprojh[i] = __float2bfloat16(wvp[i]);
    g_wprojh[65536 + i] = __float2bfloat16(wap[i]);
}

// ---------------- 3) QKV GEMM via mma.sync: C = X^T @ W^T  (M=t, N=o) ----------------
#define WCH 24     // Ws stride (rows step 12 words -> conflict-free 8-row phases)
#define XST 72     // Xs stride (rows step 4 banks)

__global__ __launch_bounds__(256, 2) void qkv_mma(const float* __restrict__ video,
                                                  const float* __restrict__ audio) {
    __shared__ __align__(16) __nv_bfloat16 Xs[256 * XST];   // [c][t]  36864 B
    __shared__ __align__(16) __nv_bfloat16 Ws[256 * WCH];   // [o][16c] 12288 B
    int b = blockIdx.z, s_out = blockIdx.y, t0 = blockIdx.x * 64;
    int str = (t0 >= VLEN);
    int tid = threadIdx.x;
    int lane = tid & 31, w = tid >> 5;
    int g = lane >> 2, qi = lane & 3;

    const float* xb; int xstride;
    if (!str) {
        int f = t0 >> 10;
        xb = video + ((size_t)(b * 16 + f) * 256) * 1024 + (t0 & 1023);
        xstride = 1024;
    } else {
        xb = audio + ((size_t)b * 256) * 4096 + (t0 - VLEN);
        xstride = 4096;
    }
    // stage X: fp32 [c][t] -> bf16 [c][t] (coalesced LDG.128, STS.64)
    {
        int lt = lane & 15, lh = lane >> 4;
#pragma unroll
        for (int pass = 0; pass < 16; pass++) {
            int c = pass * 16 + w * 2 + lh;
            float4 v = *(const float4*)(xb + (size_t)c * xstride + lt * 4);
            uint2 p = make_uint2(pack_bf16x2(v.x, v.y), pack_bf16x2(v.z, v.w));
            *(uint2*)(Xs + c * XST + lt * 4) = p;
        }
    }
    const __nv_bfloat16* Wp = g_weffh + ((size_t)(str * 2 + b) * 768 + s_out * 256) * 256;
    uint4 wpre[2];
#pragma unroll
    for (int r = 0; r < 2; r++) {
        int idx = tid + 256 * r;
        wpre[r] = *(const uint4*)(Wp + (size_t)(idx >> 1) * 256 + (idx & 1) * 8);
    }
    // ldmatrix lane bases
    u32 xs_base = (u32)__cvta_generic_to_shared(Xs)
        + (u32)(((((lane & 7) + ((lane >> 4) << 3)) * XST) + ((lane >> 3) & 1) * 8) * 2);
    u32 ws_base = (u32)__cvta_generic_to_shared(Ws)
        + (u32)(((((lane & 7) + ((lane >> 4) << 3)) * WCH) + ((lane >> 3) & 1) * 8) * 2);

    float acc[4][4][4];
#pragma unroll
    for (int mt = 0; mt < 4; mt++)
#pragma unroll
        for (int nt = 0; nt < 4; nt++)
            acc[mt][nt][0] = acc[mt][nt][1] = acc[mt][nt][2] = acc[mt][nt][3] = 0.f;

    for (int kc = 0; kc < 16; kc++) {
#pragma unroll
        for (int r = 0; r < 2; r++) {
            int idx = tid + 256 * r;
            *(uint4*)(Ws + (idx >> 1) * WCH + (idx & 1) * 8) = wpre[r];
        }
        __syncthreads();
        if (kc < 15) {
#pragma unroll
            for (int r = 0; r < 2; r++) {
                int idx = tid + 256 * r;
                wpre[r] = *(const uint4*)(Wp + (size_t)(idx >> 1) * 256 + (kc + 1) * 16 + (idx & 1) * 8);
            }
        }
        u32 a[4][4];
#pragma unroll
        for (int mt = 0; mt < 4; mt++)
            ldmx4t(a[mt][0], a[mt][1], a[mt][2], a[mt][3],
                   xs_base + (u32)((kc * 16 * XST + mt * 16) * 2));
        u32 bf[2][4];
#pragma unroll
        for (int p = 0; p < 2; p++)
            ldmx4(bf[p][0], bf[p][1], bf[p][2], bf[p][3],
                  ws_base + (u32)(((w * 32 + p * 16) * WCH) * 2));
#pragma unroll
        for (int mt = 0; mt < 4; mt++)
#pragma unroll
            for (int nt = 0; nt < 4; nt++)
                mma_bf16(acc[mt][nt], a[mt], bf[nt >> 1][(nt & 1) * 2], bf[nt >> 1][(nt & 1) * 2 + 1]);
        __syncthreads();
    }

    // epilogue: +bias, pack bf16x2, store to g_qkvt[t][64ch]
    int h = w >> 1;
    int chb = (w & 1) * 32;
    const float* be = g_beff + (size_t)(str * 2 + b) * 768 + s_out * 256 + w * 32;
    size_t hbase = (((size_t)b * 3 + s_out) * 4 + h) * (size_t)Tt * 64;
    float b0v[4], b1v[4];
#pragma unroll
    for (int nt = 0; nt < 4; nt++) {
        b0v[nt] = be[nt * 8 + 2 * qi];
        b1v[nt] = be[nt * 8 + 2 * qi + 1];
    }
#pragma unroll
    for (int mt = 0; mt < 4; mt++)
#pragma unroll
        for (int nt = 0; nt < 4; nt++) {
            int t = t0 + mt * 16 + g;
            int ch = chb + nt * 8 + 2 * qi;
            *(u32*)(g_qkvt + hbase + (size_t)t * 64 + ch) =
                pack_bf16x2(acc[mt][nt][0] + b0v[nt], acc[mt][nt][1] + b1v[nt]);
            *(u32*)(g_qkvt + hbase + (size_t)(t + 8) * 64 + ch) =
                pack_bf16x2(acc[mt][nt][2] + b0v[nt], acc[mt][nt][3] + b1v[nt]);
        }
}

// ---------------- 4) mma.sync attention (FA2, ldmatrix for K and V) ----------------
#define NKC     128
#define KSTRIDE 72

__global__ __launch_bounds__(256, 2) void attn_mma() {
    __shared__ __align__(16) __nv_bfloat16 Ks[NKC * KSTRIDE];
    __shared__ __align__(16) __nv_bfloat16 Vs[NKC * KSTRIDE];
    int tid = threadIdx.x;
    int lane = tid & 31, w = tid >> 5;
    int g = lane >> 2, qi = lane & 3;

    int id = blockIdx.x;
    int unit, qt, nchunks, tq0, tk0;
    if (id < 1024) { unit = id >> 3; qt = id & 7; nchunks = 2; }
    else { int i2 = id - 1024; unit = i2 >> 1; qt = i2 & 1; nchunks = 8; }
    int b = unit >> 6, h = (unit >> 4) & 3, f = unit & 15;
    if (id < 1024) { tq0 = f * 1024 + qt * 128; tk0 = VLEN + f * 256; }
    else           { tq0 = VLEN + f * 256 + qt * 128; tk0 = f * 1024; }

    size_t off_q = (((size_t)b * 3 + 0) * 4 + h) * (size_t)Tt * 64;
    size_t off_k = (((size_t)b * 3 + 1) * 4 + h) * (size_t)Tt * 64;
    size_t off_v = (((size_t)b * 3 + 2) * 4 + h) * (size_t)Tt * 64;

    int qbase = tq0 + w * 16;
    u32 qa[4][4];
    {
        const __nv_bfloat16* q0 = g_qkvt + off_q + (size_t)(qbase + g) * 64;
        const __nv_bfloat16* q1 = g_qkvt + off_q + (size_t)(qbase + g + 8) * 64;
#pragma unroll
        for (int s = 0; s < 4; s++) {
            qa[s][0] = *(const u32*)(q0 + 16 * s + 2 * qi);
            qa[s][1] = *(const u32*)(q1 + 16 * s + 2 * qi);
            qa[s][2] = *(const u32*)(q0 + 16 * s + 2 * qi + 8);
            qa[s][3] = *(const u32*)(q1 + 16 * s + 2 * qi + 8);
        }
    }
    // ldmatrix lane bases
    u32 ks_base = (u32)__cvta_generic_to_shared(Ks)
        + (u32)(((((lane & 7) + ((lane >> 4) << 3)) * KSTRIDE) + ((lane >> 3) & 1) * 8) * 2);
    u32 vlane = (u32)__cvta_generic_to_shared(Vs)
        + (u32)(((lane & 15) * KSTRIDE + (lane >> 4) * 8) * 2);

    float ofr[8][4];
#pragma unroll
    for (int ct = 0; ct < 8; ct++)
        ofr[ct][0] = ofr[ct][1] = ofr[ct][2] = ofr[ct][3] = 0.f;
    float mlo_r = -1e30f, mhi_r = -1e30f, llo = 0.f, lhi = 0.f;

    for (int c = 0; c < nchunks; c++) {
        int kc = tk0 + c * NKC;
        for (int m = tid; m < NKC * 8; m += 256) {
            int key = m >> 3, j = m & 7;
            *(uint4*)(Ks + key * KSTRIDE + j * 8) =
                *(const uint4*)(g_qkvt + off_k + (size_t)(kc + key) * 64 + j * 8);
            *(uint4*)(Vs + key * KSTRIDE + j * 8) =
                *(const uint4*)(g_qkvt + off_v + (size_t)(kc + key) * 64 + j * 8);
        }
        __syncthreads();

        for (int sc = 0; sc < NKC / 64; sc++) {
            float cfr[8][4];
#pragma unroll
            for (int nt = 0; nt < 8; nt++)
                cfr[nt][0] = cfr[nt][1] = cfr[nt][2] = cfr[nt][3] = 0.f;
#pragma unroll
            for (int s = 0; s < 4; s++)
#pragma unroll
                for (int p = 0; p < 4; p++) {
                    u32 r0, r1, r2, r3;
                    ldmx4(r0, r1, r2, r3,
                          ks_base + (u32)((((sc * 64 + p * 16) * KSTRIDE) + 16 * s) * 2));
                    mma_bf16(cfr[2 * p], qa[s], r0, r1);
                    mma_bf16(cfr[2 * p + 1], qa[s], r2, r3);
                }
            float mlo = -1e30f, mhi = -1e30f;
#pragma unroll
            for (int nt = 0; nt < 8; nt++) {
                mlo = fmaxf(mlo, fmaxf(cfr[nt][0], cfr[nt][1]));
                mhi = fmaxf(mhi, fmaxf(cfr[nt][2], cfr[nt][3]));
            }
            mlo *= 0.125f; mhi *= 0.125f;
            mlo = fmaxf(mlo, __shfl_xor_sync(0xffffffffu, mlo, 1));
            mlo = fmaxf(mlo, __shfl_xor_sync(0xffffffffu, mlo, 2));
            mhi = fmaxf(mhi, __shfl_xor_sync(0xffffffffu, mhi, 1));
            mhi = fmaxf(mhi, __shfl_xor_sync(0xffffffffu, mhi, 2));
            float nmlo = fmaxf(mlo_r, mlo), nmhi = fmaxf(mhi_r, mhi);
            float clo = __expf(mlo_r - nmlo), chi = __expf(mhi_r - nmhi);
            mlo_r = nmlo; mhi_r = nmhi;
            llo *= clo; lhi *= chi;
#pragma unroll
            for (int ct = 0; ct < 8; ct++) {
                ofr[ct][0] *= clo; ofr[ct][1] *= clo;
                ofr[ct][2] *= chi; ofr[ct][3] *= chi;
            }
            u32 plo[8], phi[8];
#pragma unroll
            for (int nt = 0; nt < 8; nt++) {
                float p0 = __expf(cfr[nt][0] * 0.125f - nmlo);
                float p1 = __expf(cfr[nt][1] * 0.125f - nmlo);
                float p2 = __expf(cfr[nt][2] * 0.125f - nmhi);
                float p3 = __expf(cfr[nt][3] * 0.125f - nmhi);
                llo += p0 + p1; lhi += p2 + p3;
                plo[nt] = pack_bf16x2(p0, p1);
                phi[nt] = pack_bf16x2(p2, p3);
            }
#pragma unroll
            for (int s = 0; s < 4; s++) {
                u32 pa[4] = {plo[2 * s], phi[2 * s], plo[2 * s + 1], phi[2 * s + 1]};
                u32 vrow = vlane + (u32)((sc * 64 + 16 * s) * KSTRIDE * 2);
#pragma unroll
                for (int ctp = 0; ctp < 4; ctp++) {
                    u32 r0, r1, r2, r3;
                    ldmx4t(r0, r1, r2, r3, vrow + ctp * 32);
                    mma_bf16(ofr[2 * ctp], pa, r0, r1);
                    mma_bf16(ofr[2 * ctp + 1], pa, r2, r3);
                }
            }
        }
        __syncthreads();
    }

    llo += __shfl_xor_sync(0xffffffffu, llo, 1);
    llo += __shfl_xor_sync(0xffffffffu, llo, 2);
    lhi += __shfl_xor_sync(0xffffffffu, lhi, 1);
    lhi += __shfl_xor_sync(0xffffffffu, lhi, 2);
    float ilo = 1.f / llo, ihi = 1.f / lhi;
    int q0 = qbase + g, q1 = qbase + g + 8;
    size_t r0 = ((size_t)b * Tt + q0) * 256;
    size_t r1 = ((size_t)b * Tt + q1) * 256;
#pragma unroll
    for (int ct = 0; ct < 8; ct++) {
        int ch = h * 64 + ct * 8 + 2 * qi;
        *(u32*)(g_attnh + r0 + ch) = pack_bf16x2(ofr[ct][0] * ilo, ofr[ct][1] * ilo);
        *(u32*)(g_attnh + r1 + ch) = pack_bf16x2(ofr[ct][2] * ihi, ofr[ct][3] * ihi);
    }
}

// ---------------- 5) proj via mma.sync (M=o, N=t) + residual ----------------
__global__ __launch_bounds__(256, 2) void proj_mma(
    const float* __restrict__ video, const float* __restrict__ audio,
    const float* __restrict__ bvp, const float* __restrict__ bap,
    float* __restrict__ out) {
    __shared__ __align__(16) __nv_bfloat16 Bs[64 * 264];    // attnT [t][c]
    __shared__ __align__(16) __nv_bfloat16 Wsm[256 * WCH];
    int b = blockIdx.z, t0 = blockIdx.x * 64;
    int str = (t0 >= VLEN);
    int tid = threadIdx.x;
    int lane = tid & 31, w = tid >> 5;
    int g = lane >> 2, qi = lane & 3;

    // stage attnT tile
    {
        int row = tid >> 2, seg = tid & 3;
        const uint4* src = (const uint4*)(g_attnh + ((size_t)b * Tt + t0 + row) * 256 + seg * 64);
        uint4* dst = (uint4*)(Bs + row * 264 + seg * 64);
#pragma unroll
        for (int j = 0; j < 8; j++) dst[j] = src[j];
    }
    const __nv_bfloat16* Wp = g_wprojh + (size_t)str * 65536;
    const float* bb = str ? bap : bvp;
    uint4 wpre[2];
#pragma unroll
    for (int r = 0; r < 2; r++) {
        int idx = tid + 256 * r;
        wpre[r] = *(const uint4*)(Wp + (size_t)(idx >> 1) * 256 + (idx & 1) * 8);
    }
    int o0w = (w >> 1) * 64;
    int tw = (w & 1) * 32;
    // A (non-trans, [m][k]): r1 = m+8 -> group1 rows+8; r2 = k+8 -> group2 koff 8
    u32 wa_base = (u32)__cvta_generic_to_shared(Wsm)
        + (u32)(((((lane & 7) + (((lane >> 3) & 1) << 3)) * WCH) + ((lane >> 4) << 3)) * 2);
    // B (non-trans, [n][k]): r1 = k+8 -> group1 koff 8; r2 = n+8 -> group2 rows+8
    u32 bs_base = (u32)__cvta_generic_to_shared(Bs)
        + (u32)(((((lane & 7) + ((lane >> 4) << 3)) * 264) + ((lane >> 3) & 1) * 8) * 2);

    float acc[4][4][4];
#pragma unroll
    for (int mt = 0; mt < 4; mt++)
#pragma unroll
        for (int nt = 0; nt < 4; nt++)
            acc[mt][nt][0] = acc[mt][nt][1] = acc[mt][nt][2] = acc[mt][nt][3] = 0.f;

    for (int kc = 0; kc < 16; kc++) {
#pragma unroll
        for (int r = 0; r < 2; r++) {
            int idx = tid + 256 * r;
            *(uint4*)(Wsm + (idx >> 1) * WCH + (idx & 1) * 8) = wpre[r];
        }
        __syncthreads();
        if (kc < 15) {
#pragma unroll
            for (int r = 0; r < 2; r++) {
                int idx = tid + 256 * r;
                wpre[r] = *(const uint4*)(Wp + (size_t)(idx >> 1) * 256 + (kc + 1) * 16 + (idx & 1) * 8);
            }
        }
        u32 a[4][4];
#pragma unroll
        for (int mt = 0; mt < 4; mt++)
            ldmx4(a[mt][0], a[mt][1], a[mt][2], a[mt][3],
                  wa_base + (u32)(((o0w + mt * 16) * WCH) * 2));
        u32 bf[2][4];
#pragma unroll
        for (int p = 0; p < 2; p++)
            ldmx4(bf[p][0], bf[p][1], bf[p][2], bf[p][3],
                  bs_base + (u32)((((tw + p * 16) * 264) + kc * 16) * 2));
#pragma unroll
        for (int mt = 0; mt < 4; mt++)
#pragma unroll
            for (int nt = 0; nt < 4; nt++)
                mma_bf16(acc[mt][nt], a[mt], bf[nt >> 1][(nt & 1) * 2], bf[nt >> 1][(nt & 1) * 2 + 1]);
        __syncthreads();
    }

    // epilogue: bias + residual, fp32 out
#pragma unroll
    for (int mt = 0; mt < 4; mt++) {
        int o_lo = o0w + mt * 16 + g;
        int o_hi = o_lo + 8;
        float be_lo = bb[o_lo], be_hi = bb[o_hi];
#pragma unroll
        for (int nt = 0; nt < 4; nt++) {
            int t = tw + nt * 8 + 2 * qi;
            if (!str) {
                int f = t0 >> 10;
                size_t base = ((size_t)(b * 16 + f) * 256) * 1024 + (t0 & 1023) + t;
                size_t a_lo = base + (size_t)o_lo * 1024;
                size_t a_hi = base + (size_t)o_hi * 1024;
                float2 r = *(const float2*)(video + a_lo);
                r.x += acc[mt][nt][0] + be_lo; r.y += acc[mt][nt][1] + be_lo;
                *(float2*)(out + a_lo) = r;
                float2 r2 = *(const float2*)(video + a_hi);
                r2.x += acc[mt][nt][2] + be_hi; r2.y += acc[mt][nt][3] + be_hi;
                *(float2*)(out + a_hi) = r2;
            } else {
                size_t base = ((size_t)b * 256) * 4096 + (t0 - VLEN) + t;
                size_t a_lo = base + (size_t)o_lo * 4096;
                size_t a_hi = base + (size_t)o_hi * 4096;
                float2 r = *(const float2*)(audio + a_lo);
                r.x += acc[mt][nt][0] + be_lo; r.y += acc[mt][nt][1] + be_lo;
                *(float2*)(out + 8388608 + a_lo) = r;
                float2 r2 = *(const float2*)(audio + a_hi);
                r2.x += acc[mt][nt][2] + be_hi; r2.y += acc[mt][nt][3] + be_hi;
                *(float2*)(out + 8388608 + a_hi) = r2;
            }
        }
    }
}

// ---------------- launch ----------------
extern "C" void kernel_launch(void* const* d_in, const int* in_sizes, int n_in,
                              void* d_out, int out_size) {
    const float* video  = (const float*)d_in[0];
    const float* audio  = (const float*)d_in[1];
    const float* gvs    = (const float*)d_in[2];
    const float* gvb    = (const float*)d_in[3];
    const float* gas    = (const float*)d_in[4];
    const float* gab    = (const float*)d_in[5];
    const float* w_vqkv = (const float*)d_in[6];
    const float* b_vqkv = (const float*)d_in[7];
    const float* w_aqkv = (const float*)d_in[8];
    const float* b_aqkv = (const float*)d_in[9];
    const float* w_vproj = (const float*)d_in[10];
    const float* b_vproj = (const float*)d_in[11];
    const float* w_aproj = (const float*)d_in[12];
    const float* b_aproj = (const float*)d_in[13];
    float* out = (float*)d_out;

    stats_kernel<<<128, 256>>>(video, audio);
    fold_kernel<<<3072, 256>>>(w_vqkv, b_vqkv, w_aqkv, b_aqkv, gvs, gvb, gas, gab);
    wconv_kernel<<<256, 256>>>(w_vproj, w_aproj);
    dim3 gq(320, 3, 2);
    qkv_mma<<<gq, 256>>>(video, audio);
    attn_mma<<<1280, 256>>>();
    dim3 gp(320, 1, 2);
    proj_mma<<<gp, 256>>>(video, audio, b_vproj, b_aproj, out);
}